// round 2
// baseline (speedup 1.0000x reference)
#include <cuda_runtime.h>
#include <math.h>

// Problem constants
#define HH 200
#define WW 352
#define HW 70400           // HH*WW
#define BX 32              // spatial tile width
#define BY 8               // spatial tile height
#define CO_B 32            // couts per block
#define CC 8               // cin chunk

typedef unsigned long long ull;

// Scratch (static device memory — allocation-free per harness rules)
__device__ float g_cat[4 * 128 * HW];   // cat_feat: (B=4, 2C=128, H, W)
__device__ float g_gates[128 * HW];     // gates for current step
__device__ float g_rh[64 * HW];         // reset * h

__device__ __forceinline__ ull pk(float a, float b) {
    ull r; asm("mov.b64 %0,{%1,%2};" : "=l"(r) : "f"(a), "f"(b)); return r;
}
__device__ __forceinline__ void upk(ull p, float& a, float& b) {
    asm("mov.b64 {%0,%1},%2;" : "=f"(a), "=f"(b) : "l"(p));
}
__device__ __forceinline__ void fma2(ull& d, ull a, ull b) {
    asm("fma.rn.f32x2 %0,%1,%2,%0;" : "+l"(d) : "l"(a), "l"(b));
}

// Generic fused 3x3 SAME conv over a virtual channel-concat [in0 (cin0 ch), in1 (cin1 ch)].
// mode 0: out = 0.5*(auxA + conv+b); also copies auxA into out2 (x0 -> cat_feat)
// mode 1: out = sigmoid(conv+b); additionally, for oc<64 and auxB!=null:
//         out2 = sigmoid(conv+b) * auxB   (rh = reset * h, fused)
// mode 2: out = (1-u)*h + u*tanh(conv+b), u = auxA, h = auxB (may be null -> 0)
__global__ __launch_bounds__(256, 2) void conv3x3_k(
    const float* __restrict__ in0, int cin0,
    const float* __restrict__ in1, int cin1,
    const float* __restrict__ wgt, int wcin,
    const float* __restrict__ bias,
    float* __restrict__ out,
    int mode,
    const float* __restrict__ auxA,
    const float* __restrict__ auxB,
    float* __restrict__ out2)
{
    __shared__ float  s_in[CC][BY + 2][36];      // input tile, rows 16B-aligned
    __shared__ float2 s_w2[CO_B][CC][12];        // 9 weights duplicated (w,w), padded

    const int tid  = threadIdx.x;
    const int cog  = tid >> 6;          // 0..3  (cout subgroup of 8)
    const int pxg  = tid & 63;          // 0..63
    const int prow = pxg >> 3;          // 0..7
    const int pcol = (pxg & 7) << 2;    // 0,4,...,28

    const int bx = blockIdx.x, by = blockIdx.y, cob = blockIdx.z;
    const int ox = bx * BX - 1, oy = by * BY - 1;

    ull acc2[8][2];
    const ull z = pk(0.f, 0.f);
#pragma unroll
    for (int i = 0; i < 8; i++) { acc2[i][0] = z; acc2[i][1] = z; }

    const int cin_eff = in1 ? (cin0 + cin1) : cin0;
    const int nchunks = cin_eff / CC;

    for (int ch = 0; ch < nchunks; ch++) {
        // ---- stage input tile (SAME zero padding) ----
        for (int idx = tid; idx < CC * 10 * 34; idx += 256) {
            int c   = idx / 340;
            int rem = idx - c * 340;
            int r   = rem / 34;
            int col = rem - r * 34;
            int gy = oy + r, gx = ox + col;
            float v = 0.f;
            if ((unsigned)gy < (unsigned)HH && (unsigned)gx < (unsigned)WW) {
                int gc = ch * CC + c;
                const float* src = (gc < cin0) ? (in0 + (size_t)gc * HW)
                                               : (in1 + (size_t)(gc - cin0) * HW);
                v = src[gy * WW + gx];
            }
            s_in[c][r][col] = v;
        }
        // ---- stage weights, duplicated into (w,w) pairs ----
        for (int idx = tid; idx < CO_B * CC * 9; idx += 256) {
            int co  = idx / 72;
            int rem = idx - co * 72;
            int c   = rem / 9;
            int k   = rem - c * 9;
            float w = wgt[((size_t)(cob * CO_B + co) * wcin + ch * CC + c) * 9 + k];
            s_w2[co][c][k] = make_float2(w, w);
        }
        __syncthreads();

        // ---- compute: 144 packed f32x2 FMAs per cin per thread ----
#pragma unroll
        for (int c = 0; c < CC; c++) {
#pragma unroll
            for (int r = 0; r < 3; r++) {
                const float* row = &s_in[c][prow + r][pcol];
                ull p0 = *(const ull*)(row);       // (v0,v1)
                ull p2 = *(const ull*)(row + 2);   // (v2,v3)
                ull p4 = *(const ull*)(row + 4);   // (v4,v5)
                float v0, v1, v2f, v3, v4f, v5;
                upk(p0, v0, v1); upk(p2, v2f, v3); upk(p4, v4f, v5);
                ull p1 = pk(v1, v2f);
                ull p3 = pk(v3, v4f);
                ull pr[5] = {p0, p1, p2, p3, p4};
#pragma unroll
                for (int k = 0; k < 3; k++) {
                    ull a = pr[k], b = pr[k + 2];
#pragma unroll
                    for (int co = 0; co < 8; co++) {
                        ull w = *(const ull*)&s_w2[cog * 8 + co][c][r * 3 + k];
                        fma2(acc2[co][0], a, w);
                        fma2(acc2[co][1], b, w);
                    }
                }
            }
        }
        __syncthreads();
    }

    // ---- epilogue ----
    const int y  = by * BY + prow;        // H divisible by 8
    const int xb = bx * BX + pcol;        // W divisible by 32
#pragma unroll
    for (int co = 0; co < 8; co++) {
        const int oc = cob * CO_B + cog * 8 + co;
        const float bia = bias[oc];
        const size_t base = (size_t)oc * HW + (size_t)y * WW + xb;
        float vals[4];
        upk(acc2[co][0], vals[0], vals[1]);
        upk(acc2[co][1], vals[2], vals[3]);
#pragma unroll
        for (int p = 0; p < 4; p++) {
            float v = vals[p] + bia;
            size_t o = base + p;
            if (mode == 0) {
                float x0v = auxA[o];
                out[o]  = 0.5f * (x0v + v);
                out2[o] = x0v;
            } else if (mode == 1) {
                float s = 1.f / (1.f + expf(-v));
                out[o] = s;
                if (oc < 64 && auxB) out2[o] = s * auxB[o];   // rh fused
            } else {
                float u  = auxA[o];
                float hp = auxB ? auxB[o] : 0.f;
                out[o] = (1.f - u) * hp + u * tanhf(v);
            }
        }
    }
}

extern "C" void kernel_launch(void* const* d_in, const int* in_sizes, int n_in,
                              void* d_out, int out_size)
{
    const float* x       = (const float*)d_in[0]; // (2,4,64,200,352)
    const float* msg_w   = (const float*)d_in[1]; // (64,128,3,3)
    const float* msg_b   = (const float*)d_in[2]; // (64)
    const float* gates_w = (const float*)d_in[3]; // (128,192,3,3)
    const float* gates_b = (const float*)d_in[4]; // (128)
    const float* can_w   = (const float*)d_in[5]; // (64,192,3,3)
    const float* can_b   = (const float*)d_in[6]; // (64)
    float* out = (float*)d_out;                   // (4,64,200,352)

    float *cat, *gates, *rh;
    cudaGetSymbolAddress((void**)&cat,   g_cat);
    cudaGetSymbolAddress((void**)&gates, g_gates);
    cudaGetSymbolAddress((void**)&rh,    g_rh);

    dim3 block(256);
    dim3 gridMsg(WW / BX, HH / BY, 64  / CO_B);  // 11 x 25 x 2
    dim3 gridG  (WW / BX, HH / BY, 128 / CO_B);  // 11 x 25 x 4
    dim3 gridC  (WW / BX, HH / BY, 64  / CO_B);  // 11 x 25 x 2

    // Phase A: message conv + agg + cat_feat build (per batch image)
    for (int b = 0; b < 4; b++) {
        const float* x0b = x + (size_t)b * 64 * HW;          // agent 0, batch b
        const float* x1b = x + (size_t)(4 + b) * 64 * HW;    // agent 1, batch b
        float* cat_b = cat + (size_t)b * 128 * HW;
        conv3x3_k<<<gridMsg, block>>>(
            x0b, 64, x1b, 64, msg_w, 128, msg_b,
            cat_b + (size_t)64 * HW,       // agg -> channels 64..127
            0, x0b, nullptr,
            cat_b);                        // x0 copy -> channels 0..63
    }

    // Phase B: sequential ConvGRU, 4 steps; h chains through d_out slices
    for (int t = 0; t < 4; t++) {
        const float* inp = cat + (size_t)t * 128 * HW;
        const float* hp  = t ? (out + (size_t)(t - 1) * 64 * HW) : nullptr;

        // gates = sigmoid(conv([inp, h])); rh = reset*h fused into epilogue
        conv3x3_k<<<gridG, block>>>(
            inp, 128, hp, 64, gates_w, 192, gates_b,
            gates, 1, nullptr, hp, rh);

        // cnm = tanh(conv([inp, rh])); h_next = (1-u)*h + u*cnm  -> out[t]
        conv3x3_k<<<gridC, block>>>(
            inp, 128, t ? rh : nullptr, 64, can_w, 192, can_b,
            out + (size_t)t * 64 * HW,
            2, gates + (size_t)64 * HW, hp, nullptr);
    }
}

// round 3
// speedup vs baseline: 1.2476x; 1.2476x over previous
#include <cuda_runtime.h>
#include <math.h>

// Problem constants
#define HH 200
#define WW 352
#define HW 70400           // HH*WW
#define BX 32              // spatial tile width
#define BY 8               // spatial tile height
#define CO_B 32            // couts per block
#define CC 8               // cin chunk

// Scratch (static device memory — allocation-free per harness rules)
__device__ float g_cat[4 * 128 * HW];   // cat_feat: (B=4, 2C=128, H, W)
__device__ float g_gates[128 * HW];     // gates for current step
__device__ float g_rh[64 * HW];         // reset * h

// Fused 3x3 SAME conv over a virtual channel-concat [in0 (cin0 ch), in1 (cin1 ch)].
// MODE 0: out = 0.5*(auxA + conv+b); also copies auxA into out2 (x0 -> cat_feat)
// MODE 1: out = sigmoid(conv+b); for oc<64 && auxB: out2 = out * auxB (rh fused)
// MODE 2: out = (1-u)*h + u*tanh(conv+b), u = auxA, h = auxB (may be null -> 0)
// blockIdx.z packs (img, cob): img = z / cob_per_img. Image strides sA (inputs/auxA)
// and sO (outputs) in elements.
template<int MODE>
__global__ __launch_bounds__(256, 3) void conv3x3_t(
    const float* __restrict__ in0, int cin0,
    const float* __restrict__ in1, int cin1,
    const float* __restrict__ wgt, int wcin,
    const float* __restrict__ bias,
    float* __restrict__ out,
    const float* __restrict__ auxA,
    const float* __restrict__ auxB,
    float* __restrict__ out2,
    int cob_per_img, long long sA, long long sO)
{
    __shared__ float s_in[2][CC][10][36];    // double-buffered input tile
    __shared__ float s_w [2][CO_B][CC][12];  // double-buffered weights (padded 12)

    const int tid  = threadIdx.x;
    const int cog  = tid >> 6;          // 0..3  (cout subgroup of 8)
    const int pxg  = tid & 63;          // 0..63
    const int prow = pxg >> 3;          // 0..7
    const int pcol = (pxg & 7) << 2;    // 0,4,...,28

    const int bx  = blockIdx.x, by = blockIdx.y;
    const int img = blockIdx.z / cob_per_img;
    const int cob = blockIdx.z - img * cob_per_img;

    in0 += (long long)img * sA;
    if (in1)  in1  += (long long)img * sA;
    if (auxA) auxA += (long long)img * sA;    // phase B has img==0, stride unused
    out += (long long)img * sO;
    if (out2) out2 += (long long)img * sO;

    const int ox = bx * BX - 1, oy = by * BY - 1;

    const int cin_eff = in1 ? (cin0 + cin1) : cin0;
    const int nchunks = cin_eff / CC;

    auto stage = [&](int ch, int buf) {
        // input tile with SAME zero padding (10 rows x 34 cols x CC channels)
        for (int idx = tid; idx < CC * 340; idx += 256) {
            int c   = idx / 340;
            int rem = idx - c * 340;
            int r   = rem / 34;
            int col = rem - r * 34;
            int gy = oy + r, gx = ox + col;
            float v = 0.f;
            if ((unsigned)gy < (unsigned)HH && (unsigned)gx < (unsigned)WW) {
                int gc = ch * CC + c;
                const float* src = (gc < cin0) ? (in0 + (long long)gc * HW)
                                               : (in1 + (long long)(gc - cin0) * HW);
                v = src[gy * WW + gx];
            }
            s_in[buf][c][r][col] = v;
        }
        // weights (CO_B x CC x 9)
        for (int idx = tid; idx < CO_B * CC * 9; idx += 256) {
            int co  = idx / 72;
            int rem = idx - co * 72;
            int c   = rem / 9;
            int k   = rem - c * 9;
            s_w[buf][co][c][k] =
                wgt[((long long)(cob * CO_B + co) * wcin + ch * CC + c) * 9 + k];
        }
    };

    float acc[8][4];
#pragma unroll
    for (int i = 0; i < 8; i++)
#pragma unroll
        for (int j = 0; j < 4; j++) acc[i][j] = 0.f;

    stage(0, 0);
    __syncthreads();

    for (int ch = 0; ch < nchunks; ch++) {
        const int cur = ch & 1;
        if (ch + 1 < nchunks) stage(ch + 1, cur ^ 1);

        // ---- compute on buffer cur: 288 FFMA per cin per thread ----
#pragma unroll
        for (int c = 0; c < CC; c++) {
            float4 a0 = *(const float4*)&s_in[cur][c][prow + 0][pcol];
            float2 b0 = *(const float2*)&s_in[cur][c][prow + 0][pcol + 4];
            float4 a1 = *(const float4*)&s_in[cur][c][prow + 1][pcol];
            float2 b1 = *(const float2*)&s_in[cur][c][prow + 1][pcol + 4];
            float4 a2 = *(const float4*)&s_in[cur][c][prow + 2][pcol];
            float2 b2 = *(const float2*)&s_in[cur][c][prow + 2][pcol + 4];
            float v0[6] = {a0.x, a0.y, a0.z, a0.w, b0.x, b0.y};
            float v1[6] = {a1.x, a1.y, a1.z, a1.w, b1.x, b1.y};
            float v2[6] = {a2.x, a2.y, a2.z, a2.w, b2.x, b2.y};
#pragma unroll
            for (int co = 0; co < 8; co++) {
                const float* wp = &s_w[cur][cog * 8 + co][c][0];
                float4 w0 = *(const float4*)(wp);
                float4 w1 = *(const float4*)(wp + 4);
                float4 w2 = *(const float4*)(wp + 8);   // only .x used (k=8)
#pragma unroll
                for (int p = 0; p < 4; p++) {
                    float s = acc[co][p];
                    s += v0[p + 0] * w0.x; s += v0[p + 1] * w0.y; s += v0[p + 2] * w0.z;
                    s += v1[p + 0] * w0.w; s += v1[p + 1] * w1.x; s += v1[p + 2] * w1.y;
                    s += v2[p + 0] * w1.z; s += v2[p + 1] * w1.w; s += v2[p + 2] * w2.x;
                    acc[co][p] = s;
                }
            }
        }
        __syncthreads();
    }

    // ---- epilogue ----
    const int y  = by * BY + prow;        // H divisible by 8
    const int xb = bx * BX + pcol;        // W divisible by 32
#pragma unroll
    for (int co = 0; co < 8; co++) {
        const int oc = cob * CO_B + cog * 8 + co;
        const float bia = bias[oc];
        const long long base = (long long)oc * HW + (long long)y * WW + xb;
#pragma unroll
        for (int p = 0; p < 4; p++) {
            float v = acc[co][p] + bia;
            long long o = base + p;
            if (MODE == 0) {
                float x0v = auxA[o];
                out[o]  = 0.5f * (x0v + v);
                out2[o] = x0v;
            } else if (MODE == 1) {
                float s = 1.f / (1.f + __expf(-v));
                out[o] = s;
                if (oc < 64 && auxB) out2[o] = s * auxB[o];   // rh fused
            } else {
                float u  = auxA[o];
                float hp = auxB ? auxB[o] : 0.f;
                out[o] = (1.f - u) * hp + u * tanhf(v);
            }
        }
    }
}

extern "C" void kernel_launch(void* const* d_in, const int* in_sizes, int n_in,
                              void* d_out, int out_size)
{
    const float* x       = (const float*)d_in[0]; // (2,4,64,200,352)
    const float* msg_w   = (const float*)d_in[1]; // (64,128,3,3)
    const float* msg_b   = (const float*)d_in[2]; // (64)
    const float* gates_w = (const float*)d_in[3]; // (128,192,3,3)
    const float* gates_b = (const float*)d_in[4]; // (128)
    const float* can_w   = (const float*)d_in[5]; // (64,192,3,3)
    const float* can_b   = (const float*)d_in[6]; // (64)
    float* out = (float*)d_out;                   // (4,64,200,352)

    float *cat, *gates, *rh;
    cudaGetSymbolAddress((void**)&cat,   g_cat);
    cudaGetSymbolAddress((void**)&gates, g_gates);
    cudaGetSymbolAddress((void**)&rh,    g_rh);

    // Prefer max shared-memory carveout (3 CTAs x 47.6KB per SM)
    cudaFuncSetAttribute(conv3x3_t<0>, cudaFuncAttributePreferredSharedMemoryCarveout, 100);
    cudaFuncSetAttribute(conv3x3_t<1>, cudaFuncAttributePreferredSharedMemoryCarveout, 100);
    cudaFuncSetAttribute(conv3x3_t<2>, cudaFuncAttributePreferredSharedMemoryCarveout, 100);

    dim3 block(256);

    // Phase A: message conv + agg + cat_feat build, all 4 batches in one launch
    {
        dim3 grid(WW / BX, HH / BY, 2 * 4);   // cob_per_img=2, 4 images
        conv3x3_t<0><<<grid, block>>>(
            x, 64,                              // in0 = x0 (img stride 64*HW)
            x + (size_t)4 * 64 * HW, 64,        // in1 = x1 (img stride 64*HW)
            msg_w, 128, msg_b,
            cat + (size_t)64 * HW,              // out  = agg -> channels 64..127
            x,                                  // auxA = x0
            nullptr,
            cat,                                // out2 = x0 copy -> channels 0..63
            2, (long long)64 * HW, (long long)128 * HW);
    }

    // Phase B: sequential ConvGRU, 4 steps; h chains through d_out slices
    for (int t = 0; t < 4; t++) {
        const float* inp = cat + (size_t)t * 128 * HW;
        const float* hp  = t ? (out + (size_t)(t - 1) * 64 * HW) : nullptr;

        // gates = sigmoid(conv([inp, h])); rh = reset*h fused into epilogue
        {
            dim3 grid(WW / BX, HH / BY, 4);
            conv3x3_t<1><<<grid, block>>>(
                inp, 128, hp, 64, gates_w, 192, gates_b,
                gates, nullptr, hp, rh,
                4, 0, 0);
        }

        // cnm = tanh(conv([inp, rh])); h_next = (1-u)*h + u*cnm  -> out[t]
        {
            dim3 grid(WW / BX, HH / BY, 2);
            conv3x3_t<2><<<grid, block>>>(
                inp, 128, t ? rh : nullptr, 64, can_w, 192, can_b,
                out + (size_t)t * 64 * HW,
                gates + (size_t)64 * HW, hp, nullptr,
                2, 0, 0);
        }
    }
}

// round 6
// speedup vs baseline: 2.1782x; 1.7460x over previous
#include <cuda_runtime.h>
#include <cuda_bf16.h>
#include <math.h>
#include <stdint.h>

#define HH 200
#define WW 352
#define HW 70400

// ---------------- static scratch ----------------
__device__ float g_agg[4 * 64 * HW];   // 0.5*(x0+message) per image
__device__ float g_rh [64 * HW];       // reset * h
__device__ float g_u  [64 * HW];       // update gate
// hi/lo split, transposed weights: [((c32*3+dy)*3+dx)*2+hl][n][32ci]
__device__ __nv_bfloat16 g_wt_msg  [4 * 9 * 2 * 64  * 32];
__device__ __nv_bfloat16 g_wt_gates[6 * 9 * 2 * 128 * 32];
__device__ __nv_bfloat16 g_wt_can  [6 * 9 * 2 * 64  * 32];

// ---------------- helpers ----------------
__device__ __forceinline__ uint32_t smem_u32(const void* p) {
    uint32_t a;
    asm("{ .reg .u64 t; cvta.to.shared.u64 t, %1; cvt.u32.u64 %0, t; }" : "=r"(a) : "l"(p));
    return a;
}
__device__ __forceinline__ void ldsm_x4(uint32_t* r, uint32_t addr) {
    asm volatile("ldmatrix.sync.aligned.m8n8.x4.shared.b16 {%0,%1,%2,%3}, [%4];"
        : "=r"(r[0]), "=r"(r[1]), "=r"(r[2]), "=r"(r[3]) : "r"(addr));
}
__device__ __forceinline__ void mma16816(float* d, const uint32_t* a, const uint32_t* b) {
    asm volatile("mma.sync.aligned.m16n8k16.row.col.f32.bf16.bf16.f32 "
        "{%0,%1,%2,%3},{%4,%5,%6,%7},{%8,%9},{%0,%1,%2,%3};"
        : "+f"(d[0]), "+f"(d[1]), "+f"(d[2]), "+f"(d[3])
        : "r"(a[0]), "r"(a[1]), "r"(a[2]), "r"(a[3]), "r"(b[0]), "r"(b[1]));
}

// ---------------- weight prep: transpose + bf16 hi/lo split ----------------
__global__ void prep_w_k(const float* __restrict__ w, __nv_bfloat16* __restrict__ wt,
                         int Cout, int Cin) {
    int total = (Cin / 32) * 9 * Cout * 32;
    for (int idx = blockIdx.x * blockDim.x + threadIdx.x; idx < total;
         idx += gridDim.x * blockDim.x) {
        int ci  = idx & 31;
        int n   = (idx >> 5) % Cout;
        int tap = (idx / (32 * Cout)) % 9;
        int c32 = idx / (32 * Cout * 9);
        int dy = tap / 3, dx = tap % 3;
        float v = w[(((size_t)n * Cin + c32 * 32 + ci) * 3 + dy) * 3 + dx];
        __nv_bfloat16 hi = __float2bfloat16(v);
        __nv_bfloat16 lo = __float2bfloat16(v - __bfloat162float(hi));
        size_t st = ((size_t)(c32 * 3 + dy) * 3 + dx) * 2;
        wt[((st + 0) * Cout + n) * 32 + ci] = hi;
        wt[((st + 1) * Cout + n) * 32 + ci] = lo;
    }
}

// ---------------- fused implicit-GEMM conv (HMMA) ----------------
struct Srcs { const float* p[6]; };   // 32-cin chunk base pointers

// MODE 0 (msg, N=64):   out0[img] = 0.5*(x0 + conv+b)
// MODE 1 (gates,N=128): c<64: out0 = sigmoid*h (rh); c>=64: out1 = sigmoid (u)
// MODE 2 (can,  N=64):  out0 = (1-u)*h + u*tanh(conv+b)
template<int MODE, int N>
__global__ __launch_bounds__(256, 1) void conv_mma_k(
    Srcs srcs, long long imgStride,
    const __nv_bfloat16* __restrict__ wt,
    const float* __restrict__ bias,
    int nchunks,
    const float* __restrict__ hplane,
    const float* __restrict__ uplane,
    float* __restrict__ out0,
    float* __restrict__ out1)
{
    extern __shared__ char dsm[];
    constexpr int WM = (N == 128) ? 2 : 4;      // warps along M
    constexpr int MF = 128 / (16 * WM);         // m-frags per warp (4 or 2)
    constexpr int A_BYTES = 2 * 3 * 132 * 40 * 2;

    const int tid  = threadIdx.x;
    const int warp = tid >> 5, lane = tid & 31;
    const int xt = blockIdx.x, y = blockIdx.y, img = blockIdx.z;
    const int x0 = (xt < 2) ? xt * 128 : 224;

    char* sAp = (char*)(((uintptr_t)dsm + 127) & ~(uintptr_t)127);
    __nv_bfloat16* sAe = (__nv_bfloat16*)sAp;                 // A[hl][3][132][40]
    __nv_bfloat16* sBe = (__nv_bfloat16*)(sAp + A_BYTES);     // B[hl][3dx][N][40]
    const uint32_t sA = smem_u32(sAp);
    const uint32_t sB = sA + A_BYTES;

    const int mbase = (warp % WM) * (128 / WM);
    const int nbase = (warp / WM) * 32;

    float acc[MF][4][4];
#pragma unroll
    for (int i = 0; i < MF; i++)
#pragma unroll
        for (int j = 0; j < 4; j++)
#pragma unroll
            for (int q = 0; q < 4; q++) acc[i][j][q] = 0.f;

    // lane-dependent ldmatrix address components
    const int a_row = lane & 15, a_col = (lane >> 4) * 8;
    const int b_n   = ((lane & 16) >> 1) + (lane & 7);   // n row for B ldmatrix
    const int b_k   = ((lane >> 3) & 1) * 8;             // k offset (matrices 1,3)

    for (int chunk = 0; chunk < nchunks; chunk++) {
        const float* sp = srcs.p[chunk] + (size_t)img * imgStride;
        __syncthreads();   // prior compute finished reading A (and B)

        // ---- stage A: 3 rows x 130 px x 32 ci, hi/lo ----
        for (int idx = tid; idx < 3 * 130 * 32; idx += 256) {
            int px = idx % 130;
            int ci = (idx / 130) & 31;
            int r  = idx / (130 * 32);
            int gy = y - 1 + r, gx = x0 - 1 + px;
            float v = 0.f;
            if ((unsigned)gy < (unsigned)HH && (unsigned)gx < (unsigned)WW)
                v = __ldg(sp + (size_t)ci * HW + gy * WW + gx);
            __nv_bfloat16 hi = __float2bfloat16(v);
            __nv_bfloat16 lo = __float2bfloat16(v - __bfloat162float(hi));
            int base = (r * 132 + px) * 40 + ci;
            sAe[base] = hi;
            sAe[3 * 132 * 40 + base] = lo;
        }

        for (int dy = 0; dy < 3; dy++) {
            if (dy > 0) __syncthreads();   // prior compute finished reading B

            // ---- stage B: [hl][3dx][N][32] from wt[stage][n][32] ----
            const __nv_bfloat16* ws = wt + (size_t)(chunk * 3 + dy) * 3 * 2 * N * 32;
            for (int idx = tid; idx < 3 * 2 * N * 4; idx += 256) {
                int u4 = idx & 3;
                int n  = (idx >> 2) % N;
                int hl = (idx / (4 * N)) & 1;
                int dx = idx / (8 * N);
                uint4 v = *(const uint4*)(ws + ((size_t)(dx * 2 + hl) * N + n) * 32 + u4 * 8);
                *(uint4*)(sBe + ((size_t)(hl * 3 + dx) * N + n) * 40 + u4 * 8) = v;
            }
            __syncthreads();

            // ---- compute: taps (dy fixed), dx via ldmatrix pointer shift ----
#pragma unroll
            for (int kt = 0; kt < 2; kt++) {
#pragma unroll
                for (int dx = 0; dx < 3; dx++) {
                    uint32_t a[2][MF][4];
#pragma unroll
                    for (int hl = 0; hl < 2; hl++)
#pragma unroll
                        for (int mf = 0; mf < MF; mf++) {
                            uint32_t addr = sA + (((hl * 3 + dy) * 132 +
                                (mbase + mf * 16 + a_row + dx)) * 40 +
                                kt * 16 + a_col) * 2;
                            ldsm_x4(a[hl][mf], addr);
                        }
                    uint32_t b[2][4][2];
#pragma unroll
                    for (int hl = 0; hl < 2; hl++)
#pragma unroll
                        for (int nfp = 0; nfp < 2; nfp++) {
                            uint32_t t[4];
                            // n-major tile + NON-trans ldmatrix gives the
                            // row.col B fragment (k-consecutive pairs).
                            uint32_t addr = sB + (((hl * 3 + dx) * N +
                                (nbase + nfp * 16 + b_n)) * 40 +
                                kt * 16 + b_k) * 2;
                            ldsm_x4(t, addr);
                            b[hl][nfp * 2 + 0][0] = t[0]; b[hl][nfp * 2 + 0][1] = t[1];
                            b[hl][nfp * 2 + 1][0] = t[2]; b[hl][nfp * 2 + 1][1] = t[3];
                        }
#pragma unroll
                    for (int mf = 0; mf < MF; mf++)
#pragma unroll
                        for (int nf = 0; nf < 4; nf++) {
                            mma16816(acc[mf][nf], a[0][mf], b[0][nf]);  // hi*hi
                            mma16816(acc[mf][nf], a[0][mf], b[1][nf]);  // hi*lo
                            mma16816(acc[mf][nf], a[1][mf], b[0][nf]);  // lo*hi
                        }
                }
            }
        }
    }

    // ---- epilogue ----
    const int g = lane >> 2, q = lane & 3;
#pragma unroll
    for (int mf = 0; mf < MF; mf++) {
#pragma unroll
        for (int nf = 0; nf < 4; nf++) {
#pragma unroll
            for (int v4 = 0; v4 < 4; v4++) {
                int m = mbase + mf * 16 + g + (v4 >> 1) * 8;
                int c = nbase + nf * 8 + q * 2 + (v4 & 1);
                float v = acc[mf][nf][v4] + bias[c];
                size_t px = (size_t)y * WW + (x0 + m);
                size_t o  = (size_t)c * HW + px;
                if (MODE == 0) {
                    const float* xs = srcs.p[c >> 5] + (size_t)img * imgStride;
                    (out0 + (size_t)img * 64 * HW)[o] =
                        0.5f * (xs[(size_t)(c & 31) * HW + px] + v);
                } else if (MODE == 1) {
                    float s = 1.f / (1.f + __expf(-v));
                    if (c < 64) {
                        float hv = hplane ? hplane[o] : 0.f;
                        out0[o] = s * hv;
                    } else {
                        out1[(size_t)(c - 64) * HW + px] = s;
                    }
                } else {
                    float cn = tanhf(v);
                    float uu = uplane[o];
                    float hv = hplane ? hplane[o] : 0.f;
                    out0[o] = (1.f - uu) * hv + uu * cn;
                }
            }
        }
    }
}

// ---------------- host launcher ----------------
extern "C" void kernel_launch(void* const* d_in, const int* in_sizes, int n_in,
                              void* d_out, int out_size)
{
    const float* x       = (const float*)d_in[0];
    const float* msg_w   = (const float*)d_in[1];
    const float* msg_b   = (const float*)d_in[2];
    const float* gates_w = (const float*)d_in[3];
    const float* gates_b = (const float*)d_in[4];
    const float* can_w   = (const float*)d_in[5];
    const float* can_b   = (const float*)d_in[6];
    float* out = (float*)d_out;

    float *agg, *rh, *u;
    __nv_bfloat16 *wtm, *wtg, *wtc;
    cudaGetSymbolAddress((void**)&agg, g_agg);
    cudaGetSymbolAddress((void**)&rh,  g_rh);
    cudaGetSymbolAddress((void**)&u,   g_u);
    cudaGetSymbolAddress((void**)&wtm, g_wt_msg);
    cudaGetSymbolAddress((void**)&wtg, g_wt_gates);
    cudaGetSymbolAddress((void**)&wtc, g_wt_can);

    prep_w_k<<<128, 256>>>(msg_w,   wtm, 64,  128);
    prep_w_k<<<128, 256>>>(gates_w, wtg, 128, 192);
    prep_w_k<<<128, 256>>>(can_w,   wtc, 64,  192);

    const int A_BYTES = 2 * 3 * 132 * 40 * 2;                  // 63,360
    const int smem64  = A_BYTES + 2 * 3 * 64  * 40 * 2 + 256;  // ~94.3KB
    const int smem128 = A_BYTES + 2 * 3 * 128 * 40 * 2 + 256;  // ~125.1KB
    cudaFuncSetAttribute(conv_mma_k<0,64>,  cudaFuncAttributeMaxDynamicSharedMemorySize, smem64);
    cudaFuncSetAttribute(conv_mma_k<1,128>, cudaFuncAttributeMaxDynamicSharedMemorySize, smem128);
    cudaFuncSetAttribute(conv_mma_k<2,64>,  cudaFuncAttributeMaxDynamicSharedMemorySize, smem64);

    // Phase A: message conv, all 4 images -> agg
    {
        Srcs s{};
        s.p[0] = x;                           // x0 ch 0-31
        s.p[1] = x + (size_t)32 * HW;         // x0 ch 32-63
        s.p[2] = x + (size_t)4 * 64 * HW;     // x1 ch 0-31
        s.p[3] = x + (size_t)4 * 64 * HW + (size_t)32 * HW;
        conv_mma_k<0,64><<<dim3(3, HH, 4), 256, smem64>>>(
            s, (long long)64 * HW, wtm, msg_b, 4, nullptr, nullptr, agg, nullptr);
    }

    // Phase B: sequential ConvGRU
    for (int t = 0; t < 4; t++) {
        const float* xt  = x   + (size_t)t * 64 * HW;
        const float* agt = agg + (size_t)t * 64 * HW;
        const float* hp  = t ? (out + (size_t)(t - 1) * 64 * HW) : nullptr;
        {
            Srcs s{};
            s.p[0] = xt;  s.p[1] = xt  + (size_t)32 * HW;
            s.p[2] = agt; s.p[3] = agt + (size_t)32 * HW;
            s.p[4] = hp;  s.p[5] = hp ? hp + (size_t)32 * HW : nullptr;
            conv_mma_k<1,128><<<dim3(3, HH, 1), 256, smem128>>>(
                s, 0, wtg, gates_b, t ? 6 : 4, hp, nullptr, rh, u);
        }
        {
            Srcs s{};
            s.p[0] = xt;  s.p[1] = xt  + (size_t)32 * HW;
            s.p[2] = agt; s.p[3] = agt + (size_t)32 * HW;
            s.p[4] = rh;  s.p[5] = rh + (size_t)32 * HW;
            conv_mma_k<2,64><<<dim3(3, HH, 1), 256, smem64>>>(
                s, 0, wtc, can_b, t ? 6 : 4, hp, u, out + (size_t)t * 64 * HW, nullptr);
        }
    }
}

// round 8
// speedup vs baseline: 3.2846x; 1.5079x over previous
#include <cuda_runtime.h>
#include <cuda_bf16.h>
#include <math.h>
#include <stdint.h>

#define HH 200
#define WW 352
#define HW 70400
#define LO ((size_t)HW * 64)   // hi->lo plane offset (elems)

// ---------------- static scratch ----------------
// channel-last bf16 hi/lo planes: [img][hl][HW][64]
__device__ __nv_bfloat16 g_x0s [4 * 2 * HW * 64];
__device__ __nv_bfloat16 g_x1s [4 * 2 * HW * 64];
__device__ __nv_bfloat16 g_aggs[4 * 2 * HW * 64];
__device__ __nv_bfloat16 g_hs  [2 * HW * 64];
__device__ __nv_bfloat16 g_rhs [2 * HW * 64];
__device__ float g_u[64 * HW];                 // update gate (fp32, epilogue-only)
// hi/lo split weights: [g=c32*3+dy][dx][hl][n][32ci]
__device__ __nv_bfloat16 g_wt_msg  [4 * 9 * 2 * 64  * 32];
__device__ __nv_bfloat16 g_wt_gates[6 * 9 * 2 * 128 * 32];
__device__ __nv_bfloat16 g_wt_can  [6 * 9 * 2 * 64  * 32];

// ---------------- helpers ----------------
__device__ __forceinline__ uint32_t smem_u32(const void* p) {
    uint32_t a;
    asm("{ .reg .u64 t; cvta.to.shared.u64 t, %1; cvt.u32.u64 %0, t; }" : "=r"(a) : "l"(p));
    return a;
}
__device__ __forceinline__ void cp16(uint32_t dst, const void* src) {
    asm volatile("cp.async.ca.shared.global [%0], [%1], 16;" :: "r"(dst), "l"(src));
}
__device__ __forceinline__ void cp_commit() {
    asm volatile("cp.async.commit_group;" ::: "memory");
}
template<int N_> __device__ __forceinline__ void cp_wait() {
    asm volatile("cp.async.wait_group %0;" :: "n"(N_) : "memory");
}
__device__ __forceinline__ void sts_zero16(uint32_t a) {
    asm volatile("st.shared.v4.b32 [%0], {%1,%1,%1,%1};" :: "r"(a), "r"(0u) : "memory");
}
__device__ __forceinline__ void ldsm_x4(uint32_t* r, uint32_t addr) {
    asm volatile("ldmatrix.sync.aligned.m8n8.x4.shared.b16 {%0,%1,%2,%3}, [%4];"
        : "=r"(r[0]), "=r"(r[1]), "=r"(r[2]), "=r"(r[3]) : "r"(addr));
}
__device__ __forceinline__ void mma16816(float* d, const uint32_t* a, const uint32_t* b) {
    asm volatile("mma.sync.aligned.m16n8k16.row.col.f32.bf16.bf16.f32 "
        "{%0,%1,%2,%3},{%4,%5,%6,%7},{%8,%9},{%0,%1,%2,%3};"
        : "+f"(d[0]), "+f"(d[1]), "+f"(d[2]), "+f"(d[3])
        : "r"(a[0]), "r"(a[1]), "r"(a[2]), "r"(a[3]), "r"(b[0]), "r"(b[1]));
}
__device__ __forceinline__ void split_store(__nv_bfloat16* hibase, size_t off, float v) {
    __nv_bfloat16 hi = __float2bfloat16(v);
    __nv_bfloat16 lo = __float2bfloat16(v - __bfloat162float(hi));
    hibase[off] = hi;
    hibase[LO + off] = lo;
}

// ---------------- weight prep ----------------
__global__ void prep_w_k(const float* __restrict__ w, __nv_bfloat16* __restrict__ wt,
                         int Cout, int Cin) {
    int total = (Cin / 32) * 9 * Cout * 32;
    for (int idx = blockIdx.x * blockDim.x + threadIdx.x; idx < total;
         idx += gridDim.x * blockDim.x) {
        int ci  = idx & 31;
        int n   = (idx >> 5) % Cout;
        int tap = (idx / (32 * Cout)) % 9;
        int c32 = idx / (32 * Cout * 9);
        int dy = tap / 3, dx = tap % 3;
        float v = w[(((size_t)n * Cin + c32 * 32 + ci) * 3 + dy) * 3 + dx];
        __nv_bfloat16 hi = __float2bfloat16(v);
        __nv_bfloat16 lo = __float2bfloat16(v - __bfloat162float(hi));
        size_t st = ((size_t)(c32 * 3 + dy) * 3 + dx) * 2;
        wt[((st + 0) * Cout + n) * 32 + ci] = hi;
        wt[((st + 1) * Cout + n) * 32 + ci] = lo;
    }
}

// ---------------- input prep: transpose + hi/lo split (channel-last) ----------------
__global__ __launch_bounds__(256) void prep_x_k(const float* __restrict__ x,
                                                __nv_bfloat16* __restrict__ x0s,
                                                __nv_bfloat16* __restrict__ x1s) {
    __shared__ float sf[64][132];
    const int tid = threadIdx.x;
    const int px0 = blockIdx.x * 128;
    const int img = blockIdx.y;
    const int ag  = blockIdx.z;
    const float* src = x + ((size_t)(ag * 4 + img) * 64) * HW;
    for (int i = tid; i < 64 * 128; i += 256) {
        int c = i >> 7, px = i & 127;
        sf[c][px] = src[(size_t)c * HW + px0 + px];
    }
    __syncthreads();
    __nv_bfloat16* dst = (ag ? x1s : x0s) + (size_t)img * 2 * LO;
    for (int i = tid; i < 128 * 8; i += 256) {
        int px = i >> 3, q = i & 7;
        __nv_bfloat16 hb[8], lb[8];
#pragma unroll
        for (int j = 0; j < 8; j++) {
            float v = sf[q * 8 + j][px];
            hb[j] = __float2bfloat16(v);
            lb[j] = __float2bfloat16(v - __bfloat162float(hb[j]));
        }
        size_t o = (size_t)(px0 + px) * 64 + q * 8;
        *(uint4*)(dst + o)      = *(const uint4*)hb;
        *(uint4*)(dst + LO + o) = *(const uint4*)lb;
    }
}

// ---------------- fused implicit-GEMM conv (HMMA + cp.async pipeline) ----------------
struct Srcs { const __nv_bfloat16* p[6]; };  // hi-plane chunk ptrs (+LO for lo)

// MODE 0 (msg, N=64):   agg = 0.5*(x0 + conv+b) -> split store (aggs)
// MODE 1 (gates,N=128): c<64: rhs = split(sigmoid*h); c>=64: u = sigmoid (fp32)
// MODE 2 (can,  N=64):  hn = (1-u)*h + u*tanh(conv+b) -> fp32 out + split (hs)
template<int MODE, int N>
__global__ __launch_bounds__(256, 1) void conv_mma_k(
    Srcs srcs, long long imgStride,           // elems between images (bf16 planes)
    const __nv_bfloat16* __restrict__ wt,
    const float* __restrict__ bias,
    int nchunks,
    const float* __restrict__ fpA,            // M0: x0 fp32 (img stride 64*HW); M1/M2: h fp32
    const float* __restrict__ fpB,            // M2: u fp32
    __nv_bfloat16* __restrict__ splitOut,     // M0: aggs (img stride 2*LO); M1: rhs; M2: hs
    float* __restrict__ fpOut)                // M1: u; M2: d_out slice
{
    extern __shared__ char dsm[];
    constexpr int WM = (N == 128) ? 2 : 4;
    constexpr int MF = 128 / (16 * WM);
    constexpr int A_BYTES = 2 * 3 * 132 * 40 * 2;      // 63,360
    constexpr int B_BYTES = 2 * 3 * N * 40 * 2;        // per buffer

    const int tid  = threadIdx.x;
    const int warp = tid >> 5, lane = tid & 31;
    const int xt = blockIdx.x, y = blockIdx.y, img = blockIdx.z;
    const int x0 = (xt < 2) ? xt * 128 : 224;

    char* base = (char*)(((uintptr_t)dsm + 127) & ~(uintptr_t)127);
    const uint32_t sA = smem_u32(base);
    const uint32_t sB = sA + A_BYTES;

    const int mbase = (warp % WM) * (128 / WM);
    const int nbase = (warp / WM) * 32;

    float acc[MF][4][4];
#pragma unroll
    for (int i = 0; i < MF; i++)
#pragma unroll
        for (int j = 0; j < 4; j++)
#pragma unroll
            for (int q = 0; q < 4; q++) acc[i][j][q] = 0.f;

    const int a_row = lane & 15, a_col = (lane >> 4) * 8;
    const int b_n   = ((lane & 16) >> 1) + (lane & 7);
    const int b_k   = ((lane >> 3) & 1) * 8;

    const int G = nchunks * 3;

    auto stageA = [&](int chunk) {
        const __nv_bfloat16* sp = srcs.p[chunk] + (size_t)img * imgStride;
        for (int idx = tid; idx < 3 * 130 * 2 * 4; idx += 256) {
            int quad = idx & 3;
            int hl   = (idx >> 2) & 1;
            int px   = (idx >> 3) % 130;
            int r    = idx / (130 * 2 * 4);
            int gy = y - 1 + r, gx = x0 - 1 + px;
            uint32_t dst = sA + (uint32_t)(((hl * 3 + r) * 132 + px) * 80 + quad * 16);
            if ((unsigned)gy < (unsigned)HH && (unsigned)gx < (unsigned)WW)
                cp16(dst, sp + hl * LO + (size_t)(gy * WW + gx) * 64 + quad * 8);
            else
                sts_zero16(dst);
        }
    };
    auto stageB = [&](int g, int buf) {
        const __nv_bfloat16* ws = wt + (size_t)g * 3 * 2 * N * 32;
        uint32_t bb = sB + buf * B_BYTES;
        for (int idx = tid; idx < 3 * 2 * N * 4; idx += 256) {
            int quad = idx & 3;
            int n    = (idx >> 2) % N;
            int hl   = (idx / (4 * N)) & 1;
            int dx   = idx / (8 * N);
            cp16(bb + (uint32_t)(((hl * 3 + dx) * N + n) * 80 + quad * 16),
                 ws + ((size_t)(dx * 2 + hl) * N + n) * 32 + quad * 8);
        }
    };

    stageB(0, 0);
    cp_commit();

    for (int g = 0; g < G; g++) {
        const int chunk = g / 3, dy = g - chunk * 3;
        __syncthreads();                      // all warps done with A + B[(g+1)&1]
        if (dy == 0) { stageA(chunk); cp_commit(); }
        if (g + 1 < G) { stageB(g + 1, (g + 1) & 1); cp_commit(); }
        if (g + 1 < G) cp_wait<1>(); else cp_wait<0>();
        __syncthreads();

        const uint32_t bb = sB + (g & 1) * B_BYTES;
#pragma unroll
        for (int kt = 0; kt < 2; kt++) {
#pragma unroll
            for (int dx = 0; dx < 3; dx++) {
                uint32_t a[2][MF][4];
#pragma unroll
                for (int hl = 0; hl < 2; hl++)
#pragma unroll
                    for (int mf = 0; mf < MF; mf++) {
                        uint32_t addr = sA + (uint32_t)((((hl * 3 + dy) * 132 +
                            (mbase + mf * 16 + a_row + dx)) * 40 +
                            kt * 16 + a_col) * 2);
                        ldsm_x4(a[hl][mf], addr);
                    }
                uint32_t b[2][4][2];
#pragma unroll
                for (int hl = 0; hl < 2; hl++)
#pragma unroll
                    for (int nfp = 0; nfp < 2; nfp++) {
                        uint32_t t[4];
                        uint32_t addr = bb + (uint32_t)((((hl * 3 + dx) * N +
                            (nbase + nfp * 16 + b_n)) * 40 +
                            kt * 16 + b_k) * 2);
                        ldsm_x4(t, addr);
                        b[hl][nfp * 2 + 0][0] = t[0]; b[hl][nfp * 2 + 0][1] = t[1];
                        b[hl][nfp * 2 + 1][0] = t[2]; b[hl][nfp * 2 + 1][1] = t[3];
                    }
#pragma unroll
                for (int mf = 0; mf < MF; mf++)
#pragma unroll
                    for (int nf = 0; nf < 4; nf++) {
                        mma16816(acc[mf][nf], a[0][mf], b[0][nf]);  // hi*hi
                        mma16816(acc[mf][nf], a[0][mf], b[1][nf]);  // hi*lo
                        mma16816(acc[mf][nf], a[1][mf], b[0][nf]);  // lo*hi
                    }
            }
        }
    }

    // ---- epilogue ----
    const int gq = lane >> 2, q = lane & 3;
#pragma unroll
    for (int mf = 0; mf < MF; mf++) {
#pragma unroll
        for (int nf = 0; nf < 4; nf++) {
#pragma unroll
            for (int v4 = 0; v4 < 4; v4++) {
                int m = mbase + mf * 16 + gq + (v4 >> 1) * 8;
                int c = nbase + nf * 8 + q * 2 + (v4 & 1);
                float v = acc[mf][nf][v4] + bias[c];
                size_t pix = (size_t)y * WW + (x0 + m);
                if (MODE == 0) {
                    float x0v = (fpA + (size_t)img * 64 * HW)[(size_t)c * HW + pix];
                    float a = 0.5f * (x0v + v);
                    split_store(splitOut + (size_t)img * 2 * LO, pix * 64 + c, a);
                } else if (MODE == 1) {
                    float s = 1.f / (1.f + __expf(-v));
                    if (c < 64) {
                        float hv = fpA ? fpA[(size_t)c * HW + pix] : 0.f;
                        split_store(splitOut, pix * 64 + c, s * hv);
                    } else {
                        fpOut[(size_t)(c - 64) * HW + pix] = s;
                    }
                } else {
                    float cn = tanhf(v);
                    float uu = fpB[(size_t)c * HW + pix];
                    float hv = fpA ? fpA[(size_t)c * HW + pix] : 0.f;
                    float hn = (1.f - uu) * hv + uu * cn;
                    fpOut[(size_t)c * HW + pix] = hn;
                    split_store(splitOut, pix * 64 + c, hn);
                }
            }
        }
    }
}

// ---------------- host launcher ----------------
extern "C" void kernel_launch(void* const* d_in, const int* in_sizes, int n_in,
                              void* d_out, int out_size)
{
    const float* x       = (const float*)d_in[0];
    const float* msg_w   = (const float*)d_in[1];
    const float* msg_b   = (const float*)d_in[2];
    const float* gates_w = (const float*)d_in[3];
    const float* gates_b = (const float*)d_in[4];
    const float* can_w   = (const float*)d_in[5];
    const float* can_b   = (const float*)d_in[6];
    float* out = (float*)d_out;

    __nv_bfloat16 *x0s, *x1s, *aggs, *hs, *rhs, *wtm, *wtg, *wtc;
    float* u;
    cudaGetSymbolAddress((void**)&x0s,  g_x0s);
    cudaGetSymbolAddress((void**)&x1s,  g_x1s);
    cudaGetSymbolAddress((void**)&aggs, g_aggs);
    cudaGetSymbolAddress((void**)&hs,   g_hs);
    cudaGetSymbolAddress((void**)&rhs,  g_rhs);
    cudaGetSymbolAddress((void**)&u,    g_u);
    cudaGetSymbolAddress((void**)&wtm,  g_wt_msg);
    cudaGetSymbolAddress((void**)&wtg,  g_wt_gates);
    cudaGetSymbolAddress((void**)&wtc,  g_wt_can);

    prep_w_k<<<128, 256>>>(msg_w,   wtm, 64,  128);
    prep_w_k<<<128, 256>>>(gates_w, wtg, 128, 192);
    prep_w_k<<<128, 256>>>(can_w,   wtc, 64,  192);
    prep_x_k<<<dim3(HW / 128, 4, 2), 256>>>(x, x0s, x1s);

    const int A_BYTES = 2 * 3 * 132 * 40 * 2;
    const int smem64  = A_BYTES + 2 * (2 * 3 * 64  * 40 * 2) + 256;  // ~124.8KB
    const int smem128 = A_BYTES + 2 * (2 * 3 * 128 * 40 * 2) + 256;  // ~186.5KB
    cudaFuncSetAttribute(conv_mma_k<0,64>,  cudaFuncAttributeMaxDynamicSharedMemorySize, smem64);
    cudaFuncSetAttribute(conv_mma_k<1,128>, cudaFuncAttributeMaxDynamicSharedMemorySize, smem128);
    cudaFuncSetAttribute(conv_mma_k<2,64>,  cudaFuncAttributeMaxDynamicSharedMemorySize, smem64);

    const long long imgStrideBf = 2LL * HW * 64;

    // Phase A: message conv, all 4 images -> aggs (split)
    {
        Srcs s{};
        s.p[0] = x0s;      s.p[1] = x0s + 32;
        s.p[2] = x1s;      s.p[3] = x1s + 32;
        conv_mma_k<0,64><<<dim3(3, HH, 4), 256, smem64>>>(
            s, imgStrideBf, wtm, msg_b, 4, x, nullptr, aggs, nullptr);
    }

    // Phase B: sequential ConvGRU
    for (int t = 0; t < 4; t++) {
        const __nv_bfloat16* x0t = x0s  + (size_t)t * imgStrideBf;
        const __nv_bfloat16* agt = aggs + (size_t)t * imgStrideBf;
        const float* hp = t ? (out + (size_t)(t - 1) * 64 * HW) : nullptr;
        {
            Srcs s{};
            s.p[0] = x0t; s.p[1] = x0t + 32;
            s.p[2] = agt; s.p[3] = agt + 32;
            s.p[4] = hs;  s.p[5] = hs + 32;
            conv_mma_k<1,128><<<dim3(3, HH, 1), 256, smem128>>>(
                s, 0, wtg, gates_b, t ? 6 : 4, hp, nullptr, rhs, u);
        }
        {
            Srcs s{};
            s.p[0] = x0t; s.p[1] = x0t + 32;
            s.p[2] = agt; s.p[3] = agt + 32;
            s.p[4] = rhs; s.p[5] = rhs + 32;
            conv_mma_k<2,64><<<dim3(3, HH, 1), 256, smem64>>>(
                s, 0, wtc, can_b, t ? 6 : 4, hp, u, hs, out + (size_t)t * 64 * HW);
        }
    }
}

// round 9
// speedup vs baseline: 4.2135x; 1.2828x over previous
#include <cuda_runtime.h>
#include <cuda_fp16.h>
#include <math.h>
#include <stdint.h>

#define HH 200
#define WW 352
#define HW 70400
#define LO ((size_t)HW * 64)   // hi->lo plane offset (elems)

// ---------------- static scratch ----------------
// channel-last fp16 hi/lo planes: [img][hl][HW][64]
__device__ __half g_x0s [4 * 2 * HW * 64];
__device__ __half g_x1s [4 * 2 * HW * 64];
__device__ __half g_aggs[4 * 2 * HW * 64];
__device__ __half g_hs  [2 * HW * 64];
__device__ __half g_rhs [2 * HW * 64];
__device__ float g_u[64 * HW];                 // update gate (fp32)
// fp16 weights (hi only): [g=c32*3+dy][dx][n][32ci]
__device__ __half g_wt_msg  [4 * 9 * 64  * 32];
__device__ __half g_wt_gates[6 * 9 * 128 * 32];
__device__ __half g_wt_can  [6 * 9 * 64  * 32];

// ---------------- helpers ----------------
__device__ __forceinline__ uint32_t smem_u32(const void* p) {
    uint32_t a;
    asm("{ .reg .u64 t; cvta.to.shared.u64 t, %1; cvt.u32.u64 %0, t; }" : "=r"(a) : "l"(p));
    return a;
}
__device__ __forceinline__ void cp16(uint32_t dst, const void* src) {
    asm volatile("cp.async.ca.shared.global [%0], [%1], 16;" :: "r"(dst), "l"(src));
}
__device__ __forceinline__ void cp_commit() {
    asm volatile("cp.async.commit_group;" ::: "memory");
}
template<int N_> __device__ __forceinline__ void cp_wait() {
    asm volatile("cp.async.wait_group %0;" :: "n"(N_) : "memory");
}
__device__ __forceinline__ void sts_zero16(uint32_t a) {
    asm volatile("st.shared.v4.b32 [%0], {%1,%1,%1,%1};" :: "r"(a), "r"(0u) : "memory");
}
__device__ __forceinline__ void ldsm_x4(uint32_t* r, uint32_t addr) {
    asm volatile("ldmatrix.sync.aligned.m8n8.x4.shared.b16 {%0,%1,%2,%3}, [%4];"
        : "=r"(r[0]), "=r"(r[1]), "=r"(r[2]), "=r"(r[3]) : "r"(addr));
}
__device__ __forceinline__ void mma16816(float* d, const uint32_t* a, const uint32_t* b) {
    asm volatile("mma.sync.aligned.m16n8k16.row.col.f32.f16.f16.f32 "
        "{%0,%1,%2,%3},{%4,%5,%6,%7},{%8,%9},{%0,%1,%2,%3};"
        : "+f"(d[0]), "+f"(d[1]), "+f"(d[2]), "+f"(d[3])
        : "r"(a[0]), "r"(a[1]), "r"(a[2]), "r"(a[3]), "r"(b[0]), "r"(b[1]));
}
__device__ __forceinline__ void split_store(__half* hibase, size_t off, float v) {
    __half hi = __float2half(v);
    __half lo = __float2half(v - __half2float(hi));
    hibase[off] = hi;
    hibase[LO + off] = lo;
}

// ---------------- weight prep (fp16 hi only) ----------------
__global__ void prep_w_k(const float* __restrict__ w, __half* __restrict__ wt,
                         int Cout, int Cin) {
    int total = (Cin / 32) * 9 * Cout * 32;
    for (int idx = blockIdx.x * blockDim.x + threadIdx.x; idx < total;
         idx += gridDim.x * blockDim.x) {
        int ci  = idx & 31;
        int n   = (idx >> 5) % Cout;
        int tap = (idx / (32 * Cout)) % 9;
        int c32 = idx / (32 * Cout * 9);
        int dy = tap / 3, dx = tap % 3;
        float v = w[(((size_t)n * Cin + c32 * 32 + ci) * 3 + dy) * 3 + dx];
        wt[(((size_t)(c32 * 3 + dy) * 3 + dx) * Cout + n) * 32 + ci] = __float2half(v);
    }
}

// ---------------- input prep: transpose + fp16 hi/lo split ----------------
__global__ __launch_bounds__(256) void prep_x_k(const float* __restrict__ x,
                                                __half* __restrict__ x0s,
                                                __half* __restrict__ x1s) {
    __shared__ float sf[64][132];
    const int tid = threadIdx.x;
    const int px0 = blockIdx.x * 128;
    const int img = blockIdx.y;
    const int ag  = blockIdx.z;
    const float* src = x + ((size_t)(ag * 4 + img) * 64) * HW;
    for (int i = tid; i < 64 * 128; i += 256) {
        int c = i >> 7, px = i & 127;
        sf[c][px] = src[(size_t)c * HW + px0 + px];
    }
    __syncthreads();
    __half* dst = (ag ? x1s : x0s) + (size_t)img * 2 * LO;
    for (int i = tid; i < 128 * 8; i += 256) {
        int px = i >> 3, q = i & 7;
        __half hb[8], lb[8];
#pragma unroll
        for (int j = 0; j < 8; j++) {
            float v = sf[q * 8 + j][px];
            hb[j] = __float2half(v);
            lb[j] = __float2half(v - __half2float(hb[j]));
        }
        size_t o = (size_t)(px0 + px) * 64 + q * 8;
        *(uint4*)(dst + o)      = *(const uint4*)hb;
        *(uint4*)(dst + LO + o) = *(const uint4*)lb;
    }
}

// ---------------- fused implicit-GEMM conv (HMMA fp16 2-product) ----------------
struct Srcs { const __half* p[6]; };  // hi-plane chunk ptrs (+LO for lo)

// MODE 0 (msg, N=64):   agg = 0.5*(x0 + conv+b) -> split store (aggs)
// MODE 1 (gates,N=128): c<64: rhs = split(sigmoid*h); c>=64: u = sigmoid (fp32)
// MODE 2 (can,  N=64):  hn = (1-u)*h + u*tanh(conv+b) -> fp32 out + split (hs)
template<int MODE, int N>
__global__ __launch_bounds__(256, 1) void conv_mma_k(
    Srcs srcs, long long imgStride,
    const __half* __restrict__ wt,
    const float* __restrict__ bias,
    int nchunks,
    const float* __restrict__ fpA,            // M0: x0 fp32; M1/M2: h fp32
    const float* __restrict__ fpB,            // M2: u fp32
    __half* __restrict__ splitOut,            // M0: aggs; M1: rhs; M2: hs
    float* __restrict__ fpOut)                // M1: u; M2: d_out slice
{
    extern __shared__ char dsm[];
    constexpr int WM = (N == 128) ? 2 : 4;
    constexpr int MF = 128 / (16 * WM);
    constexpr int A_BYTES = 2 * 3 * 132 * 40 * 2;      // 63,360 per buffer
    constexpr int B_BYTES = 3 * N * 40 * 2;            // hi-only per buffer

    const int tid  = threadIdx.x;
    const int warp = tid >> 5, lane = tid & 31;
    const int xt = blockIdx.x, y = blockIdx.y, img = blockIdx.z;
    const int x0 = (xt < 2) ? xt * 128 : 224;

    char* base = (char*)(((uintptr_t)dsm + 127) & ~(uintptr_t)127);
    const uint32_t sA = smem_u32(base);
    const uint32_t sB = sA + 2 * A_BYTES;

    const int mbase = (warp % WM) * (128 / WM);
    const int nbase = (warp / WM) * 32;

    float acc[MF][4][4];
#pragma unroll
    for (int i = 0; i < MF; i++)
#pragma unroll
        for (int j = 0; j < 4; j++)
#pragma unroll
            for (int q = 0; q < 4; q++) acc[i][j][q] = 0.f;

    const int a_row = lane & 15, a_col = (lane >> 4) * 8;
    const int b_n   = ((lane & 16) >> 1) + (lane & 7);
    const int b_k   = ((lane >> 3) & 1) * 8;

    const int G = nchunks * 3;

    auto stageA = [&](int chunk, int abuf) {
        const __half* sp = srcs.p[chunk] + (size_t)img * imgStride;
        uint32_t ab = sA + abuf * A_BYTES;
        for (int idx = tid; idx < 3 * 130 * 2 * 4; idx += 256) {
            int quad = idx & 3;
            int hl   = (idx >> 2) & 1;
            int px   = (idx >> 3) % 130;
            int r    = idx / (130 * 2 * 4);
            int gy = y - 1 + r, gx = x0 - 1 + px;
            uint32_t dst = ab + (uint32_t)(((hl * 3 + r) * 132 + px) * 80 + quad * 16);
            if ((unsigned)gy < (unsigned)HH && (unsigned)gx < (unsigned)WW)
                cp16(dst, sp + hl * LO + (size_t)(gy * WW + gx) * 64 + quad * 8);
            else
                sts_zero16(dst);
        }
    };
    auto stageB = [&](int g, int bbuf) {
        const __half* ws = wt + (size_t)g * 3 * N * 32;
        uint32_t bb = sB + bbuf * B_BYTES;
        for (int idx = tid; idx < 3 * N * 4; idx += 256) {
            int quad = idx & 3;
            int n    = (idx >> 2) % N;
            int dx   = idx / (4 * N);
            cp16(bb + (uint32_t)((dx * N + n) * 80 + quad * 16),
                 ws + ((size_t)dx * N + n) * 32 + quad * 8);
        }
    };

    stageA(0, 0);
    stageB(0, 0);
    cp_commit();                              // group: [A0,B0]

    for (int g = 0; g < G; g++) {
        const int chunk = g / 3, dy = g - chunk * 3;
        const int abuf = chunk & 1, bbuf = g & 1;
        const bool stA = (dy == 0 && chunk + 1 < nchunks);
        const bool stB = (g + 1 < G);

        __syncthreads();                      // all warps done reading target buffers
        if (stB) { stageB(g + 1, (g + 1) & 1); cp_commit(); }
        if (stA) { stageA(chunk + 1, abuf ^ 1); cp_commit(); }

        // groups committed after B(g)'s group
        const int allow = ((dy == 1 && chunk + 1 < nchunks) ? 1 : 0)
                        + (stB ? 1 : 0) + (stA ? 1 : 0);
        if (allow >= 2) cp_wait<2>(); else if (allow == 1) cp_wait<1>(); else cp_wait<0>();
        __syncthreads();

        const uint32_t ab = sA + abuf * A_BYTES;
        const uint32_t bb = sB + bbuf * B_BYTES;
#pragma unroll
        for (int kt = 0; kt < 2; kt++) {
#pragma unroll
            for (int dx = 0; dx < 3; dx++) {
                uint32_t a[2][MF][4];
#pragma unroll
                for (int hl = 0; hl < 2; hl++)
#pragma unroll
                    for (int mf = 0; mf < MF; mf++) {
                        uint32_t addr = ab + (uint32_t)((((hl * 3 + dy) * 132 +
                            (mbase + mf * 16 + a_row + dx)) * 40 +
                            kt * 16 + a_col) * 2);
                        ldsm_x4(a[hl][mf], addr);
                    }
                uint32_t b[4][2];
#pragma unroll
                for (int nfp = 0; nfp < 2; nfp++) {
                    uint32_t t[4];
                    uint32_t addr = bb + (uint32_t)(((dx * N +
                        (nbase + nfp * 16 + b_n)) * 40 +
                        kt * 16 + b_k) * 2);
                    ldsm_x4(t, addr);
                    b[nfp * 2 + 0][0] = t[0]; b[nfp * 2 + 0][1] = t[1];
                    b[nfp * 2 + 1][0] = t[2]; b[nfp * 2 + 1][1] = t[3];
                }
#pragma unroll
                for (int mf = 0; mf < MF; mf++)
#pragma unroll
                    for (int nf = 0; nf < 4; nf++) {
                        mma16816(acc[mf][nf], a[0][mf], b[nf]);  // hi*B
                        mma16816(acc[mf][nf], a[1][mf], b[nf]);  // lo*B
                    }
            }
        }
    }

    // ---- epilogue ----
    const int gq = lane >> 2, q = lane & 3;
#pragma unroll
    for (int mf = 0; mf < MF; mf++) {
#pragma unroll
        for (int nf = 0; nf < 4; nf++) {
#pragma unroll
            for (int v4 = 0; v4 < 4; v4++) {
                int m = mbase + mf * 16 + gq + (v4 >> 1) * 8;
                int c = nbase + nf * 8 + q * 2 + (v4 & 1);
                float v = acc[mf][nf][v4] + bias[c];
                size_t pix = (size_t)y * WW + (x0 + m);
                if (MODE == 0) {
                    float x0v = (fpA + (size_t)img * 64 * HW)[(size_t)c * HW + pix];
                    float a = 0.5f * (x0v + v);
                    split_store(splitOut + (size_t)img * 2 * LO, pix * 64 + c, a);
                } else if (MODE == 1) {
                    float s = 1.f / (1.f + __expf(-v));
                    if (c < 64) {
                        float hv = fpA ? fpA[(size_t)c * HW + pix] : 0.f;
                        split_store(splitOut, pix * 64 + c, s * hv);
                    } else {
                        fpOut[(size_t)(c - 64) * HW + pix] = s;
                    }
                } else {
                    float cn = tanhf(v);
                    float uu = fpB[(size_t)c * HW + pix];
                    float hv = fpA ? fpA[(size_t)c * HW + pix] : 0.f;
                    float hn = (1.f - uu) * hv + uu * cn;
                    fpOut[(size_t)c * HW + pix] = hn;
                    split_store(splitOut, pix * 64 + c, hn);
                }
            }
        }
    }
}

// ---------------- host launcher ----------------
extern "C" void kernel_launch(void* const* d_in, const int* in_sizes, int n_in,
                              void* d_out, int out_size)
{
    const float* x       = (const float*)d_in[0];
    const float* msg_w   = (const float*)d_in[1];
    const float* msg_b   = (const float*)d_in[2];
    const float* gates_w = (const float*)d_in[3];
    const float* gates_b = (const float*)d_in[4];
    const float* can_w   = (const float*)d_in[5];
    const float* can_b   = (const float*)d_in[6];
    float* out = (float*)d_out;

    __half *x0s, *x1s, *aggs, *hs, *rhs, *wtm, *wtg, *wtc;
    float* u;
    cudaGetSymbolAddress((void**)&x0s,  g_x0s);
    cudaGetSymbolAddress((void**)&x1s,  g_x1s);
    cudaGetSymbolAddress((void**)&aggs, g_aggs);
    cudaGetSymbolAddress((void**)&hs,   g_hs);
    cudaGetSymbolAddress((void**)&rhs,  g_rhs);
    cudaGetSymbolAddress((void**)&u,    g_u);
    cudaGetSymbolAddress((void**)&wtm,  g_wt_msg);
    cudaGetSymbolAddress((void**)&wtg,  g_wt_gates);
    cudaGetSymbolAddress((void**)&wtc,  g_wt_can);

    prep_w_k<<<128, 256>>>(msg_w,   wtm, 64,  128);
    prep_w_k<<<128, 256>>>(gates_w, wtg, 128, 192);
    prep_w_k<<<128, 256>>>(can_w,   wtc, 64,  192);
    prep_x_k<<<dim3(HW / 128, 4, 2), 256>>>(x, x0s, x1s);

    const int A_BYTES = 2 * 3 * 132 * 40 * 2;
    const int smem64  = 2 * A_BYTES + 2 * (3 * 64  * 40 * 2) + 256;  // ~157.7KB
    const int smem128 = 2 * A_BYTES + 2 * (3 * 128 * 40 * 2) + 256;  // ~188.4KB
    cudaFuncSetAttribute(conv_mma_k<0,64>,  cudaFuncAttributeMaxDynamicSharedMemorySize, smem64);
    cudaFuncSetAttribute(conv_mma_k<1,128>, cudaFuncAttributeMaxDynamicSharedMemorySize, smem128);
    cudaFuncSetAttribute(conv_mma_k<2,64>,  cudaFuncAttributeMaxDynamicSharedMemorySize, smem64);

    const long long imgStrideHf = 2LL * HW * 64;

    // Phase A: message conv, all 4 images -> aggs (split)
    {
        Srcs s{};
        s.p[0] = x0s;      s.p[1] = x0s + 32;
        s.p[2] = x1s;      s.p[3] = x1s + 32;
        conv_mma_k<0,64><<<dim3(3, HH, 4), 256, smem64>>>(
            s, imgStrideHf, wtm, msg_b, 4, x, nullptr, aggs, nullptr);
    }

    // Phase B: sequential ConvGRU
    for (int t = 0; t < 4; t++) {
        const __half* x0t = x0s  + (size_t)t * imgStrideHf;
        const __half* agt = aggs + (size_t)t * imgStrideHf;
        const float* hp = t ? (out + (size_t)(t - 1) * 64 * HW) : nullptr;
        {
            Srcs s{};
            s.p[0] = x0t; s.p[1] = x0t + 32;
            s.p[2] = agt; s.p[3] = agt + 32;
            s.p[4] = hs;  s.p[5] = hs + 32;
            conv_mma_k<1,128><<<dim3(3, HH, 1), 256, smem128>>>(
                s, 0, wtg, gates_b, t ? 6 : 4, hp, nullptr, rhs, u);
        }
        {
            Srcs s{};
            s.p[0] = x0t; s.p[1] = x0t + 32;
            s.p[2] = agt; s.p[3] = agt + 32;
            s.p[4] = rhs; s.p[5] = rhs + 32;
            conv_mma_k<2,64><<<dim3(3, HH, 1), 256, smem64>>>(
                s, 0, wtc, can_b, t ? 6 : 4, hp, u, hs, out + (size_t)t * 64 * HW);
        }
    }
}

// round 10
// speedup vs baseline: 5.0452x; 1.1974x over previous
#include <cuda_runtime.h>
#include <cuda_fp16.h>
#include <math.h>
#include <stdint.h>

#define HH 200
#define WW 352
#define HW 70400
#define LO ((size_t)HW * 64)   // hi->lo plane offset (elems)

// ---------------- static scratch ----------------
// channel-last fp16 hi/lo planes: [img][hl][HW][64]
__device__ __half g_x0s [4 * 2 * HW * 64];
__device__ __half g_x1s [4 * 2 * HW * 64];
__device__ __half g_aggs[4 * 2 * HW * 64];
__device__ __half g_hs  [2 * HW * 64];
__device__ __half g_rhs [2 * HW * 64];
__device__ float g_u[64 * HW];                 // update gate (fp32)
// fp16 weights (hi only): [g=c32*3+dy][dx][n][32ci]
__device__ __half g_wt_msg  [4 * 9 * 64  * 32];
__device__ __half g_wt_gates[6 * 9 * 128 * 32];
__device__ __half g_wt_can  [6 * 9 * 64  * 32];

// ---------------- helpers ----------------
__device__ __forceinline__ uint32_t smem_u32(const void* p) {
    uint32_t a;
    asm("{ .reg .u64 t; cvta.to.shared.u64 t, %1; cvt.u32.u64 %0, t; }" : "=r"(a) : "l"(p));
    return a;
}
__device__ __forceinline__ void cp16(uint32_t dst, const void* src) {
    asm volatile("cp.async.ca.shared.global [%0], [%1], 16;" :: "r"(dst), "l"(src));
}
__device__ __forceinline__ void cp_commit() {
    asm volatile("cp.async.commit_group;" ::: "memory");
}
template<int N_> __device__ __forceinline__ void cp_wait() {
    asm volatile("cp.async.wait_group %0;" :: "n"(N_) : "memory");
}
__device__ __forceinline__ void sts_zero16(uint32_t a) {
    asm volatile("st.shared.v4.b32 [%0], {%1,%1,%1,%1};" :: "r"(a), "r"(0u) : "memory");
}
__device__ __forceinline__ void ldsm_x4(uint32_t* r, uint32_t addr) {
    asm volatile("ldmatrix.sync.aligned.m8n8.x4.shared.b16 {%0,%1,%2,%3}, [%4];"
        : "=r"(r[0]), "=r"(r[1]), "=r"(r[2]), "=r"(r[3]) : "r"(addr));
}
__device__ __forceinline__ void mma16816(float* d, const uint32_t* a, const uint32_t* b) {
    asm volatile("mma.sync.aligned.m16n8k16.row.col.f32.f16.f16.f32 "
        "{%0,%1,%2,%3},{%4,%5,%6,%7},{%8,%9},{%0,%1,%2,%3};"
        : "+f"(d[0]), "+f"(d[1]), "+f"(d[2]), "+f"(d[3])
        : "r"(a[0]), "r"(a[1]), "r"(a[2]), "r"(a[3]), "r"(b[0]), "r"(b[1]));
}
__device__ __forceinline__ void split_store(__half* hibase, size_t off, float v) {
    __half hi = __float2half(v);
    __half lo = __float2half(v - __half2float(hi));
    hibase[off] = hi;
    hibase[LO + off] = lo;
}

// ---------------- weight prep (fp16 hi only) ----------------
__global__ void prep_w_k(const float* __restrict__ w, __half* __restrict__ wt,
                         int Cout, int Cin) {
    int total = (Cin / 32) * 9 * Cout * 32;
    for (int idx = blockIdx.x * blockDim.x + threadIdx.x; idx < total;
         idx += gridDim.x * blockDim.x) {
        int ci  = idx & 31;
        int n   = (idx >> 5) % Cout;
        int tap = (idx / (32 * Cout)) % 9;
        int c32 = idx / (32 * Cout * 9);
        int dy = tap / 3, dx = tap % 3;
        float v = w[(((size_t)n * Cin + c32 * 32 + ci) * 3 + dy) * 3 + dx];
        wt[(((size_t)(c32 * 3 + dy) * 3 + dx) * Cout + n) * 32 + ci] = __float2half(v);
    }
}

// ---------------- input prep: transpose + fp16 hi/lo split ----------------
__global__ __launch_bounds__(256) void prep_x_k(const float* __restrict__ x,
                                                __half* __restrict__ x0s,
                                                __half* __restrict__ x1s) {
    __shared__ float sf[64][132];
    const int tid = threadIdx.x;
    const int px0 = blockIdx.x * 128;
    const int img = blockIdx.y;
    const int ag  = blockIdx.z;
    const float* src = x + ((size_t)(ag * 4 + img) * 64) * HW;
    for (int i = tid; i < 64 * 128; i += 256) {
        int c = i >> 7, px = i & 127;
        sf[c][px] = src[(size_t)c * HW + px0 + px];
    }
    __syncthreads();
    __half* dst = (ag ? x1s : x0s) + (size_t)img * 2 * LO;
    for (int i = tid; i < 128 * 8; i += 256) {
        int px = i >> 3, q = i & 7;
        __half hb[8], lb[8];
#pragma unroll
        for (int j = 0; j < 8; j++) {
            float v = sf[q * 8 + j][px];
            hb[j] = __float2half(v);
            lb[j] = __float2half(v - __half2float(hb[j]));
        }
        size_t o = (size_t)(px0 + px) * 64 + q * 8;
        *(uint4*)(dst + o)      = *(const uint4*)hb;
        *(uint4*)(dst + LO + o) = *(const uint4*)lb;
    }
}

// ---------------- fused implicit-GEMM conv (HMMA fp16 2-product) ----------------
struct Srcs { const __half* p[6]; };  // hi-plane chunk ptrs (+LO for lo)

// MODE 0 (msg, N=64):   agg = 0.5*(x0 + conv+b) -> split store (aggs)
// MODE 1 (gates,N=128): c<64: rhs = split(sigmoid*h); c>=64: u = sigmoid (fp32)
// MODE 2 (can,  N=64):  hn = (1-u)*h + u*tanh(conv+b) -> fp32 out + split (hs)
template<int MODE, int N>
__global__ __launch_bounds__(256, 2) void conv_mma_k(
    Srcs srcs, long long imgStride,
    const __half* __restrict__ wt,
    const float* __restrict__ bias,
    int nchunks,
    const float* __restrict__ fpA,            // M0: x0 fp32; M1/M2: h fp32
    const float* __restrict__ fpB,            // M2: u fp32
    __half* __restrict__ splitOut,            // M0: aggs; M1: rhs; M2: hs
    float* __restrict__ fpOut)                // M1: u; M2: d_out slice
{
    extern __shared__ char dsm[];
    constexpr int WM = (N == 128) ? 2 : 4;
    constexpr int MF = 128 / (16 * WM);
    constexpr int A_BYTES = 2 * 3 * 132 * 40 * 2;      // 63,360 (single buffer)

    const int tid  = threadIdx.x;
    const int warp = tid >> 5, lane = tid & 31;
    const int xt = blockIdx.x, y = blockIdx.y, img = blockIdx.z;
    const int x0 = (xt < 2) ? xt * 128 : 224;

    char* base = (char*)(((uintptr_t)dsm + 127) & ~(uintptr_t)127);
    const uint32_t sA = smem_u32(base);
    const uint32_t sB = sA + A_BYTES;

    const int mbase = (warp % WM) * (128 / WM);
    const int nbase = (warp / WM) * 32;

    float acc[MF][4][4];
#pragma unroll
    for (int i = 0; i < MF; i++)
#pragma unroll
        for (int j = 0; j < 4; j++)
#pragma unroll
            for (int q = 0; q < 4; q++) acc[i][j][q] = 0.f;

    const int a_row = lane & 15, a_col = (lane >> 4) * 8;
    const int b_n   = ((lane & 16) >> 1) + (lane & 7);
    const int b_k   = ((lane >> 3) & 1) * 8;

    const int G = nchunks * 3;

    auto stageA = [&](int chunk) {
        const __half* sp = srcs.p[chunk] + (size_t)img * imgStride;
        for (int idx = tid; idx < 3 * 130 * 2 * 4; idx += 256) {
            int quad = idx & 3;
            int hl   = (idx >> 2) & 1;
            int px   = (idx >> 3) % 130;
            int r    = idx / (130 * 2 * 4);
            int gy = y - 1 + r, gx = x0 - 1 + px;
            uint32_t dst = sA + (uint32_t)(((hl * 3 + r) * 132 + px) * 80 + quad * 16);
            if ((unsigned)gy < (unsigned)HH && (unsigned)gx < (unsigned)WW)
                cp16(dst, sp + hl * LO + (size_t)(gy * WW + gx) * 64 + quad * 8);
            else
                sts_zero16(dst);
        }
    };
    auto stageB = [&](int g) {
        const __half* ws = wt + (size_t)g * 3 * N * 32;
        for (int idx = tid; idx < 3 * N * 4; idx += 256) {
            int quad = idx & 3;
            int n    = (idx >> 2) % N;
            int dx   = idx / (4 * N);
            cp16(sB + (uint32_t)((dx * N + n) * 80 + quad * 16),
                 ws + ((size_t)dx * N + n) * 32 + quad * 8);
        }
    };

    for (int g = 0; g < G; g++) {
        const int chunk = g / 3, dy = g - chunk * 3;

        __syncthreads();                      // previous compute done reading smem
        if (dy == 0) stageA(chunk);
        stageB(g);
        cp_commit();
        cp_wait<0>();
        __syncthreads();                      // staged data visible to all

#pragma unroll
        for (int kt = 0; kt < 2; kt++) {
#pragma unroll
            for (int dx = 0; dx < 3; dx++) {
                uint32_t a[2][MF][4];
#pragma unroll
                for (int hl = 0; hl < 2; hl++)
#pragma unroll
                    for (int mf = 0; mf < MF; mf++) {
                        uint32_t addr = sA + (uint32_t)((((hl * 3 + dy) * 132 +
                            (mbase + mf * 16 + a_row + dx)) * 40 +
                            kt * 16 + a_col) * 2);
                        ldsm_x4(a[hl][mf], addr);
                    }
#pragma unroll
                for (int nfp = 0; nfp < 2; nfp++) {
                    uint32_t t[4];
                    uint32_t addr = sB + (uint32_t)(((dx * N +
                        (nbase + nfp * 16 + b_n)) * 40 +
                        kt * 16 + b_k) * 2);
                    ldsm_x4(t, addr);
#pragma unroll
                    for (int half_ = 0; half_ < 2; half_++) {
                        uint32_t bfrag[2] = {t[half_ * 2], t[half_ * 2 + 1]};
                        int nf = nfp * 2 + half_;
#pragma unroll
                        for (int mf = 0; mf < MF; mf++) {
                            mma16816(acc[mf][nf], a[0][mf], bfrag);  // hi*B
                            mma16816(acc[mf][nf], a[1][mf], bfrag);  // lo*B
                        }
                    }
                }
            }
        }
    }

    // ---- epilogue ----
    const int gq = lane >> 2, q = lane & 3;
#pragma unroll
    for (int mf = 0; mf < MF; mf++) {
#pragma unroll
        for (int nf = 0; nf < 4; nf++) {
#pragma unroll
            for (int v4 = 0; v4 < 4; v4++) {
                int m = mbase + mf * 16 + gq + (v4 >> 1) * 8;
                int c = nbase + nf * 8 + q * 2 + (v4 & 1);
                float v = acc[mf][nf][v4] + bias[c];
                size_t pix = (size_t)y * WW + (x0 + m);
                if (MODE == 0) {
                    float x0v = (fpA + (size_t)img * 64 * HW)[(size_t)c * HW + pix];
                    float a = 0.5f * (x0v + v);
                    split_store(splitOut + (size_t)img * 2 * LO, pix * 64 + c, a);
                } else if (MODE == 1) {
                    float s = 1.f / (1.f + __expf(-v));
                    if (c < 64) {
                        float hv = fpA ? fpA[(size_t)c * HW + pix] : 0.f;
                        split_store(splitOut, pix * 64 + c, s * hv);
                    } else {
                        fpOut[(size_t)(c - 64) * HW + pix] = s;
                    }
                } else {
                    float cn = tanhf(v);
                    float uu = fpB[(size_t)c * HW + pix];
                    float hv = fpA ? fpA[(size_t)c * HW + pix] : 0.f;
                    float hn = (1.f - uu) * hv + uu * cn;
                    fpOut[(size_t)c * HW + pix] = hn;
                    split_store(splitOut, pix * 64 + c, hn);
                }
            }
        }
    }
}

// ---------------- host launcher ----------------
extern "C" void kernel_launch(void* const* d_in, const int* in_sizes, int n_in,
                              void* d_out, int out_size)
{
    const float* x       = (const float*)d_in[0];
    const float* msg_w   = (const float*)d_in[1];
    const float* msg_b   = (const float*)d_in[2];
    const float* gates_w = (const float*)d_in[3];
    const float* gates_b = (const float*)d_in[4];
    const float* can_w   = (const float*)d_in[5];
    const float* can_b   = (const float*)d_in[6];
    float* out = (float*)d_out;

    __half *x0s, *x1s, *aggs, *hs, *rhs, *wtm, *wtg, *wtc;
    float* u;
    cudaGetSymbolAddress((void**)&x0s,  g_x0s);
    cudaGetSymbolAddress((void**)&x1s,  g_x1s);
    cudaGetSymbolAddress((void**)&aggs, g_aggs);
    cudaGetSymbolAddress((void**)&hs,   g_hs);
    cudaGetSymbolAddress((void**)&rhs,  g_rhs);
    cudaGetSymbolAddress((void**)&u,    g_u);
    cudaGetSymbolAddress((void**)&wtm,  g_wt_msg);
    cudaGetSymbolAddress((void**)&wtg,  g_wt_gates);
    cudaGetSymbolAddress((void**)&wtc,  g_wt_can);

    prep_w_k<<<128, 256>>>(msg_w,   wtm, 64,  128);
    prep_w_k<<<128, 256>>>(gates_w, wtg, 128, 192);
    prep_w_k<<<128, 256>>>(can_w,   wtc, 64,  192);
    prep_x_k<<<dim3(HW / 128, 4, 2), 256>>>(x, x0s, x1s);

    const int A_BYTES = 2 * 3 * 132 * 40 * 2;                 // 63,360
    const int smem64  = A_BYTES + 3 * 64  * 40 * 2 + 256;     // ~79.0KB  -> 2 CTAs/SM
    const int smem128 = A_BYTES + 3 * 128 * 40 * 2 + 256;     // ~94.3KB  -> 2 CTAs/SM
    cudaFuncSetAttribute(conv_mma_k<0,64>,  cudaFuncAttributeMaxDynamicSharedMemorySize, smem64);
    cudaFuncSetAttribute(conv_mma_k<1,128>, cudaFuncAttributeMaxDynamicSharedMemorySize, smem128);
    cudaFuncSetAttribute(conv_mma_k<2,64>,  cudaFuncAttributeMaxDynamicSharedMemorySize, smem64);

    const long long imgStrideHf = 2LL * HW * 64;

    // Phase A: message conv, all 4 images -> aggs (split)
    {
        Srcs s{};
        s.p[0] = x0s;      s.p[1] = x0s + 32;
        s.p[2] = x1s;      s.p[3] = x1s + 32;
        conv_mma_k<0,64><<<dim3(3, HH, 4), 256, smem64>>>(
            s, imgStrideHf, wtm, msg_b, 4, x, nullptr, aggs, nullptr);
    }

    // Phase B: sequential ConvGRU
    for (int t = 0; t < 4; t++) {
        const __half* x0t = x0s  + (size_t)t * imgStrideHf;
        const __half* agt = aggs + (size_t)t * imgStrideHf;
        const float* hp = t ? (out + (size_t)(t - 1) * 64 * HW) : nullptr;
        {
            Srcs s{};
            s.p[0] = x0t; s.p[1] = x0t + 32;
            s.p[2] = agt; s.p[3] = agt + 32;
            s.p[4] = hs;  s.p[5] = hs + 32;
            conv_mma_k<1,128><<<dim3(3, HH, 1), 256, smem128>>>(
                s, 0, wtg, gates_b, t ? 6 : 4, hp, nullptr, rhs, u);
        }
        {
            Srcs s{};
            s.p[0] = x0t; s.p[1] = x0t + 32;
            s.p[2] = agt; s.p[3] = agt + 32;
            s.p[4] = rhs; s.p[5] = rhs + 32;
            conv_mma_k<2,64><<<dim3(3, HH, 1), 256, smem64>>>(
                s, 0, wtc, can_b, t ? 6 : 4, hp, u, hs, out + (size_t)t * 64 * HW);
        }
    }
}

// round 11
// speedup vs baseline: 5.4939x; 1.0889x over previous
#include <cuda_runtime.h>
#include <cuda_fp16.h>
#include <math.h>
#include <stdint.h>

#define HH 200
#define WW 352
#define HW 70400
#define LO ((size_t)HW * 64)   // hi->lo plane offset (elems)

// ---------------- static scratch ----------------
__device__ __half g_x0s [4 * 2 * HW * 64];
__device__ __half g_x1s [4 * 2 * HW * 64];
__device__ __half g_aggs[4 * 2 * HW * 64];
__device__ __half g_hs  [2 * HW * 64];
__device__ __half g_rhs [2 * HW * 64];
__device__ float g_u[64 * HW];
// fp16 weights (hi only): [g=c32*3+dy][dx][n][32ci]
__device__ __half g_wt_msg  [4 * 9 * 64  * 32];
__device__ __half g_wt_gates[6 * 9 * 128 * 32];
__device__ __half g_wt_can  [6 * 9 * 64  * 32];

// ---------------- helpers ----------------
__device__ __forceinline__ uint32_t smem_u32(const void* p) {
    uint32_t a;
    asm("{ .reg .u64 t; cvta.to.shared.u64 t, %1; cvt.u32.u64 %0, t; }" : "=r"(a) : "l"(p));
    return a;
}
__device__ __forceinline__ void cp16(uint32_t dst, const void* src) {
    asm volatile("cp.async.ca.shared.global [%0], [%1], 16;" :: "r"(dst), "l"(src));
}
__device__ __forceinline__ void cp_commit() {
    asm volatile("cp.async.commit_group;" ::: "memory");
}
template<int N_> __device__ __forceinline__ void cp_wait() {
    asm volatile("cp.async.wait_group %0;" :: "n"(N_) : "memory");
}
__device__ __forceinline__ void sts_zero16(uint32_t a) {
    asm volatile("st.shared.v4.b32 [%0], {%1,%1,%1,%1};" :: "r"(a), "r"(0u) : "memory");
}
__device__ __forceinline__ void ldsm_x4(uint32_t* r, uint32_t addr) {
    asm volatile("ldmatrix.sync.aligned.m8n8.x4.shared.b16 {%0,%1,%2,%3}, [%4];"
        : "=r"(r[0]), "=r"(r[1]), "=r"(r[2]), "=r"(r[3]) : "r"(addr));
}
__device__ __forceinline__ void mma16816(float* d, const uint32_t* a, const uint32_t* b) {
    asm volatile("mma.sync.aligned.m16n8k16.row.col.f32.f16.f16.f32 "
        "{%0,%1,%2,%3},{%4,%5,%6,%7},{%8,%9},{%0,%1,%2,%3};"
        : "+f"(d[0]), "+f"(d[1]), "+f"(d[2]), "+f"(d[3])
        : "r"(a[0]), "r"(a[1]), "r"(a[2]), "r"(a[3]), "r"(b[0]), "r"(b[1]));
}
__device__ __forceinline__ float fast_tanh(float v) {
    float e = __expf(2.f * v);
    return 1.f - 2.f / (e + 1.f);
}
// packed split store of adjacent channel pair (off must be 2-elem aligned)
__device__ __forceinline__ void split_store2(__half* hibase, size_t off, float v0, float v1) {
    __half h0 = __float2half(v0), h1 = __float2half(v1);
    __half l0 = __float2half(v0 - __half2float(h0));
    __half l1 = __float2half(v1 - __half2float(h1));
    __half2 hp; hp.x = h0; hp.y = h1;
    __half2 lp; lp.x = l0; lp.y = l1;
    *(__half2*)(hibase + off)      = hp;
    *(__half2*)(hibase + LO + off) = lp;
}

// ---------------- weight prep (fp16 hi only) ----------------
__global__ void prep_w_k(const float* __restrict__ w, __half* __restrict__ wt,
                         int Cout, int Cin) {
    int total = (Cin / 32) * 9 * Cout * 32;
    for (int idx = blockIdx.x * blockDim.x + threadIdx.x; idx < total;
         idx += gridDim.x * blockDim.x) {
        int ci  = idx & 31;
        int n   = (idx >> 5) % Cout;
        int tap = (idx / (32 * Cout)) % 9;
        int c32 = idx / (32 * Cout * 9);
        int dy = tap / 3, dx = tap % 3;
        float v = w[(((size_t)n * Cin + c32 * 32 + ci) * 3 + dy) * 3 + dx];
        wt[(((size_t)(c32 * 3 + dy) * 3 + dx) * Cout + n) * 32 + ci] = __float2half(v);
    }
}

// ---------------- input prep: transpose + fp16 hi/lo split ----------------
__global__ __launch_bounds__(256) void prep_x_k(const float* __restrict__ x,
                                                __half* __restrict__ x0s,
                                                __half* __restrict__ x1s) {
    __shared__ float sf[64][132];
    const int tid = threadIdx.x;
    const int px0 = blockIdx.x * 128;
    const int img = blockIdx.y;
    const int ag  = blockIdx.z;
    const float* src = x + ((size_t)(ag * 4 + img) * 64) * HW;
    for (int i = tid; i < 64 * 128; i += 256) {
        int c = i >> 7, px = i & 127;
        sf[c][px] = src[(size_t)c * HW + px0 + px];
    }
    __syncthreads();
    __half* dst = (ag ? x1s : x0s) + (size_t)img * 2 * LO;
    for (int i = tid; i < 128 * 8; i += 256) {
        int px = i >> 3, q = i & 7;
        __half hb[8], lb[8];
#pragma unroll
        for (int j = 0; j < 8; j++) {
            float v = sf[q * 8 + j][px];
            hb[j] = __float2half(v);
            lb[j] = __float2half(v - __half2float(hb[j]));
        }
        size_t o = (size_t)(px0 + px) * 64 + q * 8;
        *(uint4*)(dst + o)      = *(const uint4*)hb;
        *(uint4*)(dst + LO + o) = *(const uint4*)lb;
    }
}

// ---------------- fused implicit-GEMM conv (HMMA fp16 2-product) ----------------
struct Srcs { const __half* p[6]; };

// MODE 0 (msg, N=64):   agg = 0.5*(x0 + conv+b) -> split store (aggs)
// MODE 1 (gates,N=128): c<64: rhs = split(sigmoid*h); c>=64: u = sigmoid (fp32)
// MODE 2 (can,  N=64):  hn = (1-u)*h + u*tanh(conv+b) -> fp32 out + split (hs)
template<int MODE, int N>
__global__ __launch_bounds__(256, 2) void conv_mma_k(
    Srcs srcs, long long imgStride,
    const __half* __restrict__ wt,
    const float* __restrict__ bias,
    int nchunks,
    const float* __restrict__ fpA,
    const float* __restrict__ fpB,
    __half* __restrict__ splitOut,
    float* __restrict__ fpOut)
{
    extern __shared__ char dsm[];
    constexpr int WM = (N == 128) ? 2 : 4;
    constexpr int MF = 128 / (16 * WM);
    constexpr int A_BYTES = 2 * 3 * 132 * 40 * 2;      // 63,360
    constexpr int B_BYTES = 3 * N * 40 * 2;
    constexpr bool DB = (N == 64);                     // B double-buffer fits only N=64

    const int tid  = threadIdx.x;
    const int warp = tid >> 5, lane = tid & 31;
    const int xt = blockIdx.x, y = blockIdx.y, img = blockIdx.z;
    const int x0 = (xt < 2) ? xt * 128 : 224;

    char* base = (char*)(((uintptr_t)dsm + 127) & ~(uintptr_t)127);
    const uint32_t sA = smem_u32(base);
    const uint32_t sB = sA + A_BYTES;

    const int mbase = (warp % WM) * (128 / WM);
    const int nbase = (warp / WM) * 32;

    float acc[MF][4][4];
#pragma unroll
    for (int i = 0; i < MF; i++)
#pragma unroll
        for (int j = 0; j < 4; j++)
#pragma unroll
            for (int q = 0; q < 4; q++) acc[i][j][q] = 0.f;

    const int a_row = lane & 15, a_col = (lane >> 4) * 8;
    const int b_n   = ((lane & 16) >> 1) + (lane & 7);
    const int b_k   = ((lane >> 3) & 1) * 8;

    const int G = nchunks * 3;

    auto stageA = [&](int chunk) {
        const __half* sp = srcs.p[chunk] + (size_t)img * imgStride;
        for (int idx = tid; idx < 3 * 130 * 2 * 4; idx += 256) {
            int quad = idx & 3;
            int hl   = (idx >> 2) & 1;
            int px   = (idx >> 3) % 130;
            int r    = idx / (130 * 2 * 4);
            int gy = y - 1 + r, gx = x0 - 1 + px;
            uint32_t dst = sA + (uint32_t)(((hl * 3 + r) * 132 + px) * 80 + quad * 16);
            if ((unsigned)gy < (unsigned)HH && (unsigned)gx < (unsigned)WW)
                cp16(dst, sp + hl * LO + (size_t)(gy * WW + gx) * 64 + quad * 8);
            else
                sts_zero16(dst);
        }
    };
    auto stageB = [&](int g, int bbuf) {
        const __half* ws = wt + (size_t)g * 3 * N * 32;
        uint32_t bb = sB + bbuf * B_BYTES;
        for (int idx = tid; idx < 3 * N * 4; idx += 256) {
            int quad = idx & 3;
            int n    = (idx >> 2) % N;
            int dx   = idx / (4 * N);
            cp16(bb + (uint32_t)((dx * N + n) * 80 + quad * 16),
                 ws + ((size_t)dx * N + n) * 32 + quad * 8);
        }
    };

    if (DB) { stageB(0, 0); cp_commit(); }

    for (int g = 0; g < G; g++) {
        const int chunk = g / 3, dy = g - chunk * 3;
        const int bbuf = DB ? (g & 1) : 0;

        __syncthreads();                      // prior compute done reading A + target B buf
        if (dy == 0) { stageA(chunk); cp_commit(); }
        if (DB) {
            if (g + 1 < G) { stageB(g + 1, (g + 1) & 1); cp_commit(); }
            if (g + 1 < G) cp_wait<1>(); else cp_wait<0>();   // keep B(g+1) in flight
        } else {
            stageB(g, 0); cp_commit();
            cp_wait<0>();
        }
        __syncthreads();

        const uint32_t bb = sB + bbuf * B_BYTES;
#pragma unroll
        for (int kt = 0; kt < 2; kt++) {
#pragma unroll
            for (int dx = 0; dx < 3; dx++) {
                uint32_t a[2][MF][4];
#pragma unroll
                for (int hl = 0; hl < 2; hl++)
#pragma unroll
                    for (int mf = 0; mf < MF; mf++) {
                        uint32_t addr = sA + (uint32_t)((((hl * 3 + dy) * 132 +
                            (mbase + mf * 16 + a_row + dx)) * 40 +
                            kt * 16 + a_col) * 2);
                        ldsm_x4(a[hl][mf], addr);
                    }
#pragma unroll
                for (int nfp = 0; nfp < 2; nfp++) {
                    uint32_t t[4];
                    uint32_t addr = bb + (uint32_t)(((dx * N +
                        (nbase + nfp * 16 + b_n)) * 40 +
                        kt * 16 + b_k) * 2);
                    ldsm_x4(t, addr);
#pragma unroll
                    for (int half_ = 0; half_ < 2; half_++) {
                        uint32_t bfrag[2] = {t[half_ * 2], t[half_ * 2 + 1]};
                        int nf = nfp * 2 + half_;
#pragma unroll
                        for (int mf = 0; mf < MF; mf++) {
                            mma16816(acc[mf][nf], a[0][mf], bfrag);  // hi*B
                            mma16816(acc[mf][nf], a[1][mf], bfrag);  // lo*B
                        }
                    }
                }
            }
        }
    }

    // ---- epilogue (c pairs packed) ----
    const int gq = lane >> 2, q = lane & 3;
#pragma unroll
    for (int mf = 0; mf < MF; mf++) {
#pragma unroll
        for (int nf = 0; nf < 4; nf++) {
#pragma unroll
            for (int mh = 0; mh < 2; mh++) {          // m half (v4>>1)
                int m  = mbase + mf * 16 + gq + mh * 8;
                int c0 = nbase + nf * 8 + q * 2;      // even; c1 = c0+1
                float v0 = acc[mf][nf][mh * 2 + 0] + bias[c0];
                float v1 = acc[mf][nf][mh * 2 + 1] + bias[c0 + 1];
                size_t pix = (size_t)y * WW + (x0 + m);
                size_t o0 = (size_t)c0 * HW + pix;
                size_t o1 = o0 + HW;
                if (MODE == 0) {
                    const float* xs = fpA + (size_t)img * 64 * HW;
                    float a0 = 0.5f * (xs[o0] + v0);
                    float a1 = 0.5f * (xs[o1] + v1);
                    split_store2(splitOut + (size_t)img * 2 * LO, pix * 64 + c0, a0, a1);
                } else if (MODE == 1) {
                    float s0 = 1.f / (1.f + __expf(-v0));
                    float s1 = 1.f / (1.f + __expf(-v1));
                    if (c0 < 64) {
                        float h0 = fpA ? fpA[o0] : 0.f;
                        float h1 = fpA ? fpA[o1] : 0.f;
                        split_store2(splitOut, pix * 64 + c0, s0 * h0, s1 * h1);
                    } else {
                        fpOut[(size_t)(c0 - 64) * HW + pix] = s0;
                        fpOut[(size_t)(c0 - 63) * HW + pix] = s1;
                    }
                } else {
                    float cn0 = fast_tanh(v0), cn1 = fast_tanh(v1);
                    float u0 = fpB[o0], u1 = fpB[o1];
                    float h0 = fpA ? fpA[o0] : 0.f;
                    float h1 = fpA ? fpA[o1] : 0.f;
                    float hn0 = (1.f - u0) * h0 + u0 * cn0;
                    float hn1 = (1.f - u1) * h1 + u1 * cn1;
                    fpOut[o0] = hn0;
                    fpOut[o1] = hn1;
                    split_store2(splitOut, pix * 64 + c0, hn0, hn1);
                }
            }
        }
    }
}

// ---------------- host launcher ----------------
extern "C" void kernel_launch(void* const* d_in, const int* in_sizes, int n_in,
                              void* d_out, int out_size)
{
    const float* x       = (const float*)d_in[0];
    const float* msg_w   = (const float*)d_in[1];
    const float* msg_b   = (const float*)d_in[2];
    const float* gates_w = (const float*)d_in[3];
    const float* gates_b = (const float*)d_in[4];
    const float* can_w   = (const float*)d_in[5];
    const float* can_b   = (const float*)d_in[6];
    float* out = (float*)d_out;

    __half *x0s, *x1s, *aggs, *hs, *rhs, *wtm, *wtg, *wtc;
    float* u;
    cudaGetSymbolAddress((void**)&x0s,  g_x0s);
    cudaGetSymbolAddress((void**)&x1s,  g_x1s);
    cudaGetSymbolAddress((void**)&aggs, g_aggs);
    cudaGetSymbolAddress((void**)&hs,   g_hs);
    cudaGetSymbolAddress((void**)&rhs,  g_rhs);
    cudaGetSymbolAddress((void**)&u,    g_u);
    cudaGetSymbolAddress((void**)&wtm,  g_wt_msg);
    cudaGetSymbolAddress((void**)&wtg,  g_wt_gates);
    cudaGetSymbolAddress((void**)&wtc,  g_wt_can);

    prep_w_k<<<128, 256>>>(msg_w,   wtm, 64,  128);
    prep_w_k<<<128, 256>>>(gates_w, wtg, 128, 192);
    prep_w_k<<<128, 256>>>(can_w,   wtc, 64,  192);
    prep_x_k<<<dim3(HW / 128, 4, 2), 256>>>(x, x0s, x1s);

    const int A_BYTES = 2 * 3 * 132 * 40 * 2;                 // 63,360
    const int smem64  = A_BYTES + 2 * (3 * 64 * 40 * 2) + 256;  // ~94.3KB -> 2 CTAs/SM
    const int smem128 = A_BYTES + 3 * 128 * 40 * 2 + 256;       // ~94.3KB -> 2 CTAs/SM
    cudaFuncSetAttribute(conv_mma_k<0,64>,  cudaFuncAttributeMaxDynamicSharedMemorySize, smem64);
    cudaFuncSetAttribute(conv_mma_k<1,128>, cudaFuncAttributeMaxDynamicSharedMemorySize, smem128);
    cudaFuncSetAttribute(conv_mma_k<2,64>,  cudaFuncAttributeMaxDynamicSharedMemorySize, smem64);

    const long long imgStrideHf = 2LL * HW * 64;

    // Phase A: message conv, all 4 images -> aggs (split)
    {
        Srcs s{};
        s.p[0] = x0s;      s.p[1] = x0s + 32;
        s.p[2] = x1s;      s.p[3] = x1s + 32;
        conv_mma_k<0,64><<<dim3(3, HH, 4), 256, smem64>>>(
            s, imgStrideHf, wtm, msg_b, 4, x, nullptr, aggs, nullptr);
    }

    // Phase B: sequential ConvGRU
    for (int t = 0; t < 4; t++) {
        const __half* x0t = x0s  + (size_t)t * imgStrideHf;
        const __half* agt = aggs + (size_t)t * imgStrideHf;
        const float* hp = t ? (out + (size_t)(t - 1) * 64 * HW) : nullptr;
        {
            Srcs s{};
            s.p[0] = x0t; s.p[1] = x0t + 32;
            s.p[2] = agt; s.p[3] = agt + 32;
            s.p[4] = hs;  s.p[5] = hs + 32;
            conv_mma_k<1,128><<<dim3(3, HH, 1), 256, smem128>>>(
                s, 0, wtg, gates_b, t ? 6 : 4, hp, nullptr, rhs, u);
        }
        {
            Srcs s{};
            s.p[0] = x0t; s.p[1] = x0t + 32;
            s.p[2] = agt; s.p[3] = agt + 32;
            s.p[4] = rhs; s.p[5] = rhs + 32;
            conv_mma_k<2,64><<<dim3(3, HH, 1), 256, smem64>>>(
                s, 0, wtc, can_b, t ? 6 : 4, hp, u, hs, out + (size_t)t * 64 * HW);
        }
    }
}

// round 12
// speedup vs baseline: 5.5691x; 1.0137x over previous
#include <cuda_runtime.h>
#include <cuda_fp16.h>
#include <math.h>
#include <stdint.h>

#define HH 200
#define WW 352
#define HW 70400
#define LO ((size_t)HW * 64)   // hi->lo plane offset (elems)

// ---------------- static scratch ----------------
__device__ __half g_x0s [4 * 2 * HW * 64];
__device__ __half g_x1s [4 * 2 * HW * 64];
__device__ __half g_aggs[4 * 2 * HW * 64];
__device__ __half g_hs  [2 * HW * 64];
__device__ __half g_rhs [2 * HW * 64];
__device__ float g_u[HW * 64];                 // update gate, CHANNEL-LAST [pix][c]
// fp16 weights (hi only): [g=c32*3+dy][dx][n][32ci]
__device__ __half g_wt_msg  [4 * 9 * 64  * 32];
__device__ __half g_wt_gates[6 * 9 * 128 * 32];
__device__ __half g_wt_can  [6 * 9 * 64  * 32];

// ---------------- helpers ----------------
__device__ __forceinline__ uint32_t smem_u32(const void* p) {
    uint32_t a;
    asm("{ .reg .u64 t; cvta.to.shared.u64 t, %1; cvt.u32.u64 %0, t; }" : "=r"(a) : "l"(p));
    return a;
}
__device__ __forceinline__ void cp16(uint32_t dst, const void* src) {
    asm volatile("cp.async.ca.shared.global [%0], [%1], 16;" :: "r"(dst), "l"(src));
}
__device__ __forceinline__ void cp_commit() {
    asm volatile("cp.async.commit_group;" ::: "memory");
}
template<int N_> __device__ __forceinline__ void cp_wait() {
    asm volatile("cp.async.wait_group %0;" :: "n"(N_) : "memory");
}
__device__ __forceinline__ void sts_zero16(uint32_t a) {
    asm volatile("st.shared.v4.b32 [%0], {%1,%1,%1,%1};" :: "r"(a), "r"(0u) : "memory");
}
__device__ __forceinline__ void ldsm_x4(uint32_t* r, uint32_t addr) {
    asm volatile("ldmatrix.sync.aligned.m8n8.x4.shared.b16 {%0,%1,%2,%3}, [%4];"
        : "=r"(r[0]), "=r"(r[1]), "=r"(r[2]), "=r"(r[3]) : "r"(addr));
}
__device__ __forceinline__ void mma16816(float* d, const uint32_t* a, const uint32_t* b) {
    asm volatile("mma.sync.aligned.m16n8k16.row.col.f32.f16.f16.f32 "
        "{%0,%1,%2,%3},{%4,%5,%6,%7},{%8,%9},{%0,%1,%2,%3};"
        : "+f"(d[0]), "+f"(d[1]), "+f"(d[2]), "+f"(d[3])
        : "r"(a[0]), "r"(a[1]), "r"(a[2]), "r"(a[3]), "r"(b[0]), "r"(b[1]));
}
__device__ __forceinline__ float fast_tanh(float v) {
    float e = __expf(2.f * v);
    return 1.f - 2.f / (e + 1.f);
}
__device__ __forceinline__ void split_store2(__half* hibase, size_t off, float v0, float v1) {
    __half h0 = __float2half(v0), h1 = __float2half(v1);
    __half l0 = __float2half(v0 - __half2float(h0));
    __half l1 = __float2half(v1 - __half2float(h1));
    __half2 hp; hp.x = h0; hp.y = h1;
    __half2 lp; lp.x = l0; lp.y = l1;
    *(__half2*)(hibase + off)      = hp;
    *(__half2*)(hibase + LO + off) = lp;
}

// ---------------- weight prep (fp16 hi only) ----------------
__global__ void prep_w_k(const float* __restrict__ w, __half* __restrict__ wt,
                         int Cout, int Cin) {
    int total = (Cin / 32) * 9 * Cout * 32;
    for (int idx = blockIdx.x * blockDim.x + threadIdx.x; idx < total;
         idx += gridDim.x * blockDim.x) {
        int ci  = idx & 31;
        int n   = (idx >> 5) % Cout;
        int tap = (idx / (32 * Cout)) % 9;
        int c32 = idx / (32 * Cout * 9);
        int dy = tap / 3, dx = tap % 3;
        float v = w[(((size_t)n * Cin + c32 * 32 + ci) * 3 + dy) * 3 + dx];
        wt[(((size_t)(c32 * 3 + dy) * 3 + dx) * Cout + n) * 32 + ci] = __float2half(v);
    }
}

// ---------------- input prep: transpose + fp16 hi/lo split ----------------
__global__ __launch_bounds__(256) void prep_x_k(const float* __restrict__ x,
                                                __half* __restrict__ x0s,
                                                __half* __restrict__ x1s) {
    __shared__ float sf[64][132];
    const int tid = threadIdx.x;
    const int px0 = blockIdx.x * 128;
    const int img = blockIdx.y;
    const int ag  = blockIdx.z;
    const float* src = x + ((size_t)(ag * 4 + img) * 64) * HW;
    for (int i = tid; i < 64 * 128; i += 256) {
        int c = i >> 7, px = i & 127;
        sf[c][px] = src[(size_t)c * HW + px0 + px];
    }
    __syncthreads();
    __half* dst = (ag ? x1s : x0s) + (size_t)img * 2 * LO;
    for (int i = tid; i < 128 * 8; i += 256) {
        int px = i >> 3, q = i & 7;
        __half hb[8], lb[8];
#pragma unroll
        for (int j = 0; j < 8; j++) {
            float v = sf[q * 8 + j][px];
            hb[j] = __float2half(v);
            lb[j] = __float2half(v - __half2float(hb[j]));
        }
        size_t o = (size_t)(px0 + px) * 64 + q * 8;
        *(uint4*)(dst + o)      = *(const uint4*)hb;
        *(uint4*)(dst + LO + o) = *(const uint4*)lb;
    }
}

// ---------------- fused implicit-GEMM conv (HMMA fp16 2-product) ----------------
struct Srcs { const __half* p[6]; };

// MODE 0 (msg, N=64):   agg = 0.5*(x0 + conv+b) -> split store (aggs)
// MODE 1 (gates,N=128): c<64: rhs = split(sigmoid*h); c>=64: u = sigmoid (ch-last fp32)
// MODE 2 (can,  N=64):  hn = (1-u)*h + u*tanh(conv+b) -> fp32 out + split (hs)
template<int MODE, int N>
__global__ __launch_bounds__(256, 2) void conv_mma_k(
    Srcs srcs, long long imgStride,
    const __half* __restrict__ wt,
    const float* __restrict__ bias,
    int nchunks,
    const float* __restrict__ fpA,            // M0: x0 fp32; M1/M2: h fp32 (NCHW)
    const float* __restrict__ fpB,            // M2: u (channel-last)
    __half* __restrict__ splitOut,            // M0: aggs; M1: rhs; M2: hs
    float* __restrict__ fpOut)                // M1: u (ch-last); M2: d_out slice
{
    extern __shared__ char dsm[];
    constexpr int WM  = 4;                    // warps along M (both N)
    constexpr int MF  = 2;                    // m-frags per warp
    constexpr int NPW = N / 2;                // n per warp (WN = 2)
    constexpr int NFP = NPW / 16;             // B ldsm.x4 count
    constexpr int NF  = NPW / 8;              // n-frags (8 wide)
    constexpr int A_BYTES = 2 * 3 * 132 * 40 * 2;      // 63,360
    constexpr int B_BYTES = 3 * N * 40 * 2;
    constexpr bool DB = (N == 64);

    const int tid  = threadIdx.x;
    const int warp = tid >> 5, lane = tid & 31;
    const int xt = blockIdx.x, y = blockIdx.y, img = blockIdx.z;
    const int x0 = (xt < 2) ? xt * 128 : 224;

    char* base = (char*)(((uintptr_t)dsm + 127) & ~(uintptr_t)127);
    const uint32_t sA = smem_u32(base);
    const uint32_t sB = sA + A_BYTES;

    const int mbase = (warp & 3) * 32;        // warp%WM * 128/WM
    const int nbase = (warp >> 2) * NPW;

    float acc[MF][NF][4];
#pragma unroll
    for (int i = 0; i < MF; i++)
#pragma unroll
        for (int j = 0; j < NF; j++)
#pragma unroll
            for (int q = 0; q < 4; q++) acc[i][j][q] = 0.f;

    const int a_row = lane & 15, a_col = (lane >> 4) * 8;
    const int b_n   = ((lane & 16) >> 1) + (lane & 7);
    const int b_k   = ((lane >> 3) & 1) * 8;

    const int G = nchunks * 3;

    auto stageA = [&](int chunk) {
        const __half* sp = srcs.p[chunk] + (size_t)img * imgStride;
        for (int idx = tid; idx < 3 * 130 * 2 * 4; idx += 256) {
            int quad = idx & 3;
            int hl   = (idx >> 2) & 1;
            int px   = (idx >> 3) % 130;
            int r    = idx / (130 * 2 * 4);
            int gy = y - 1 + r, gx = x0 - 1 + px;
            uint32_t dst = sA + (uint32_t)(((hl * 3 + r) * 132 + px) * 80 + quad * 16);
            if ((unsigned)gy < (unsigned)HH && (unsigned)gx < (unsigned)WW)
                cp16(dst, sp + hl * LO + (size_t)(gy * WW + gx) * 64 + quad * 8);
            else
                sts_zero16(dst);
        }
    };
    auto stageB = [&](int g, int bbuf) {
        const __half* ws = wt + (size_t)g * 3 * N * 32;
        uint32_t bb = sB + bbuf * B_BYTES;
        for (int idx = tid; idx < 3 * N * 4; idx += 256) {
            int quad = idx & 3;
            int n    = (idx >> 2) % N;
            int dx   = idx / (4 * N);
            cp16(bb + (uint32_t)((dx * N + n) * 80 + quad * 16),
                 ws + ((size_t)dx * N + n) * 32 + quad * 8);
        }
    };

    if (DB) { stageB(0, 0); cp_commit(); }

    for (int g = 0; g < G; g++) {
        const int chunk = g / 3, dy = g - chunk * 3;
        const int bbuf = DB ? (g & 1) : 0;

        __syncthreads();
        if (dy == 0) { stageA(chunk); cp_commit(); }
        if (DB) {
            if (g + 1 < G) { stageB(g + 1, (g + 1) & 1); cp_commit(); }
            if (g + 1 < G) cp_wait<1>(); else cp_wait<0>();
        } else {
            stageB(g, 0); cp_commit();
            cp_wait<0>();
        }
        __syncthreads();

        const uint32_t bb = sB + bbuf * B_BYTES;
#pragma unroll
        for (int kt = 0; kt < 2; kt++) {
#pragma unroll
            for (int dx = 0; dx < 3; dx++) {
                uint32_t a[2][MF][4];
#pragma unroll
                for (int hl = 0; hl < 2; hl++)
#pragma unroll
                    for (int mf = 0; mf < MF; mf++) {
                        uint32_t addr = sA + (uint32_t)((((hl * 3 + dy) * 132 +
                            (mbase + mf * 16 + a_row + dx)) * 40 +
                            kt * 16 + a_col) * 2);
                        ldsm_x4(a[hl][mf], addr);
                    }
#pragma unroll
                for (int nfp = 0; nfp < NFP; nfp++) {
                    uint32_t t[4];
                    uint32_t addr = bb + (uint32_t)(((dx * N +
                        (nbase + nfp * 16 + b_n)) * 40 +
                        kt * 16 + b_k) * 2);
                    ldsm_x4(t, addr);
#pragma unroll
                    for (int half_ = 0; half_ < 2; half_++) {
                        uint32_t bfrag[2] = {t[half_ * 2], t[half_ * 2 + 1]};
                        int nf = nfp * 2 + half_;
#pragma unroll
                        for (int mf = 0; mf < MF; mf++) {
                            mma16816(acc[mf][nf], a[0][mf], bfrag);  // hi*B
                            mma16816(acc[mf][nf], a[1][mf], bfrag);  // lo*B
                        }
                    }
                }
            }
        }
    }

    // ---- epilogue (c pairs packed) ----
    const int gq = lane >> 2, q = lane & 3;
#pragma unroll
    for (int mf = 0; mf < MF; mf++) {
#pragma unroll
        for (int nf = 0; nf < NF; nf++) {
#pragma unroll
            for (int mh = 0; mh < 2; mh++) {
                int m  = mbase + mf * 16 + gq + mh * 8;
                int c0 = nbase + nf * 8 + q * 2;
                float v0 = acc[mf][nf][mh * 2 + 0] + bias[c0];
                float v1 = acc[mf][nf][mh * 2 + 1] + bias[c0 + 1];
                size_t pix = (size_t)y * WW + (x0 + m);
                size_t o0 = (size_t)c0 * HW + pix;
                size_t o1 = o0 + HW;
                if (MODE == 0) {
                    const float* xs = fpA + (size_t)img * 64 * HW;
                    float a0 = 0.5f * (xs[o0] + v0);
                    float a1 = 0.5f * (xs[o1] + v1);
                    split_store2(splitOut + (size_t)img * 2 * LO, pix * 64 + c0, a0, a1);
                } else if (MODE == 1) {
                    float s0 = 1.f / (1.f + __expf(-v0));
                    float s1 = 1.f / (1.f + __expf(-v1));
                    if (c0 < 64) {
                        float h0 = fpA ? fpA[o0] : 0.f;
                        float h1 = fpA ? fpA[o1] : 0.f;
                        split_store2(splitOut, pix * 64 + c0, s0 * h0, s1 * h1);
                    } else {
                        // channel-last u: coalesced paired store
                        float2 up; up.x = s0; up.y = s1;
                        *(float2*)(fpOut + pix * 64 + (c0 - 64)) = up;
                    }
                } else {
                    float cn0 = fast_tanh(v0), cn1 = fast_tanh(v1);
                    float2 up = *(const float2*)(fpB + pix * 64 + c0);   // channel-last u
                    float h0 = fpA ? fpA[o0] : 0.f;
                    float h1 = fpA ? fpA[o1] : 0.f;
                    float hn0 = (1.f - up.x) * h0 + up.x * cn0;
                    float hn1 = (1.f - up.y) * h1 + up.y * cn1;
                    fpOut[o0] = hn0;
                    fpOut[o1] = hn1;
                    split_store2(splitOut, pix * 64 + c0, hn0, hn1);
                }
            }
        }
    }
}

// ---------------- host launcher ----------------
extern "C" void kernel_launch(void* const* d_in, const int* in_sizes, int n_in,
                              void* d_out, int out_size)
{
    const float* x       = (const float*)d_in[0];
    const float* msg_w   = (const float*)d_in[1];
    const float* msg_b   = (const float*)d_in[2];
    const float* gates_w = (const float*)d_in[3];
    const float* gates_b = (const float*)d_in[4];
    const float* can_w   = (const float*)d_in[5];
    const float* can_b   = (const float*)d_in[6];
    float* out = (float*)d_out;

    __half *x0s, *x1s, *aggs, *hs, *rhs, *wtm, *wtg, *wtc;
    float* u;
    cudaGetSymbolAddress((void**)&x0s,  g_x0s);
    cudaGetSymbolAddress((void**)&x1s,  g_x1s);
    cudaGetSymbolAddress((void**)&aggs, g_aggs);
    cudaGetSymbolAddress((void**)&hs,   g_hs);
    cudaGetSymbolAddress((void**)&rhs,  g_rhs);
    cudaGetSymbolAddress((void**)&u,    g_u);
    cudaGetSymbolAddress((void**)&wtm,  g_wt_msg);
    cudaGetSymbolAddress((void**)&wtg,  g_wt_gates);
    cudaGetSymbolAddress((void**)&wtc,  g_wt_can);

    prep_w_k<<<128, 256>>>(msg_w,   wtm, 64,  128);
    prep_w_k<<<128, 256>>>(gates_w, wtg, 128, 192);
    prep_w_k<<<128, 256>>>(can_w,   wtc, 64,  192);
    prep_x_k<<<dim3(HW / 128, 4, 2), 256>>>(x, x0s, x1s);

    const int A_BYTES = 2 * 3 * 132 * 40 * 2;                   // 63,360
    const int smem64  = A_BYTES + 2 * (3 * 64 * 40 * 2) + 256;  // ~94.3KB -> 2 CTAs/SM
    const int smem128 = A_BYTES + 3 * 128 * 40 * 2 + 256;       // ~94.3KB -> 2 CTAs/SM
    cudaFuncSetAttribute(conv_mma_k<0,64>,  cudaFuncAttributeMaxDynamicSharedMemorySize, smem64);
    cudaFuncSetAttribute(conv_mma_k<1,128>, cudaFuncAttributeMaxDynamicSharedMemorySize, smem128);
    cudaFuncSetAttribute(conv_mma_k<2,64>,  cudaFuncAttributeMaxDynamicSharedMemorySize, smem64);

    const long long imgStrideHf = 2LL * HW * 64;

    // Phase A: message conv, all 4 images -> aggs (split)
    {
        Srcs s{};
        s.p[0] = x0s;      s.p[1] = x0s + 32;
        s.p[2] = x1s;      s.p[3] = x1s + 32;
        conv_mma_k<0,64><<<dim3(3, HH, 4), 256, smem64>>>(
            s, imgStrideHf, wtm, msg_b, 4, x, nullptr, aggs, nullptr);
    }

    // Phase B: sequential ConvGRU
    for (int t = 0; t < 4; t++) {
        const __half* x0t = x0s  + (size_t)t * imgStrideHf;
        const __half* agt = aggs + (size_t)t * imgStrideHf;
        const float* hp = t ? (out + (size_t)(t - 1) * 64 * HW) : nullptr;
        {
            Srcs s{};
            s.p[0] = x0t; s.p[1] = x0t + 32;
            s.p[2] = agt; s.p[3] = agt + 32;
            s.p[4] = hs;  s.p[5] = hs + 32;
            conv_mma_k<1,128><<<dim3(3, HH, 1), 256, smem128>>>(
                s, 0, wtg, gates_b, t ? 6 : 4, hp, nullptr, rhs, u);
        }
        {
            Srcs s{};
            s.p[0] = x0t; s.p[1] = x0t + 32;
            s.p[2] = agt; s.p[3] = agt + 32;
            s.p[4] = rhs; s.p[5] = rhs + 32;
            conv_mma_k<2,64><<<dim3(3, HH, 1), 256, smem64>>>(
                s, 0, wtc, can_b, t ? 6 : 4, hp, u, hs, out + (size_t)t * 64 * HW);
        }
    }
}

// round 13
// speedup vs baseline: 5.6182x; 1.0088x over previous
#include <cuda_runtime.h>
#include <cuda_fp16.h>
#include <math.h>
#include <stdint.h>

#define HH 200
#define WW 352
#define HW 70400
#define LO ((size_t)HW * 64)   // hi->lo plane offset (elems)

// ---------------- static scratch ----------------
__device__ __half g_x0s [4 * 2 * HW * 64];
__device__ __half g_x1s [4 * 2 * HW * 64];
__device__ __half g_aggs[4 * 2 * HW * 64];
__device__ __half g_hs  [2 * HW * 64];
__device__ __half g_rhs [2 * HW * 64];
__device__ float g_u[HW * 64];                 // update gate, CHANNEL-LAST [pix][c]
// fp16 weights (hi only): [g=c32*3+dy][dx][n][32ci]
__device__ __half g_wt_msg  [4 * 9 * 64  * 32];
__device__ __half g_wt_gates[6 * 9 * 128 * 32];
__device__ __half g_wt_can  [6 * 9 * 64  * 32];

// ---------------- helpers ----------------
__device__ __forceinline__ uint32_t smem_u32(const void* p) {
    uint32_t a;
    asm("{ .reg .u64 t; cvta.to.shared.u64 t, %1; cvt.u32.u64 %0, t; }" : "=r"(a) : "l"(p));
    return a;
}
__device__ __forceinline__ void cp16(uint32_t dst, const void* src) {
    asm volatile("cp.async.ca.shared.global [%0], [%1], 16;" :: "r"(dst), "l"(src));
}
__device__ __forceinline__ void cp_commit() {
    asm volatile("cp.async.commit_group;" ::: "memory");
}
template<int N_> __device__ __forceinline__ void cp_wait() {
    asm volatile("cp.async.wait_group %0;" :: "n"(N_) : "memory");
}
__device__ __forceinline__ void sts_zero16(uint32_t a) {
    asm volatile("st.shared.v4.b32 [%0], {%1,%1,%1,%1};" :: "r"(a), "r"(0u) : "memory");
}
__device__ __forceinline__ void ldsm_x4(uint32_t* r, uint32_t addr) {
    asm volatile("ldmatrix.sync.aligned.m8n8.x4.shared.b16 {%0,%1,%2,%3}, [%4];"
        : "=r"(r[0]), "=r"(r[1]), "=r"(r[2]), "=r"(r[3]) : "r"(addr));
}
__device__ __forceinline__ void mma16816(float* d, const uint32_t* a, const uint32_t* b) {
    asm volatile("mma.sync.aligned.m16n8k16.row.col.f32.f16.f16.f32 "
        "{%0,%1,%2,%3},{%4,%5,%6,%7},{%8,%9},{%0,%1,%2,%3};"
        : "+f"(d[0]), "+f"(d[1]), "+f"(d[2]), "+f"(d[3])
        : "r"(a[0]), "r"(a[1]), "r"(a[2]), "r"(a[3]), "r"(b[0]), "r"(b[1]));
}
__device__ __forceinline__ float fast_tanh(float v) {
    float e = __expf(2.f * v);
    return 1.f - 2.f / (e + 1.f);
}
__device__ __forceinline__ void split_store2(__half* hibase, size_t off, float v0, float v1) {
    __half h0 = __float2half(v0), h1 = __float2half(v1);
    __half l0 = __float2half(v0 - __half2float(h0));
    __half l1 = __float2half(v1 - __half2float(h1));
    __half2 hp; hp.x = h0; hp.y = h1;
    __half2 lp; lp.x = l0; lp.y = l1;
    *(__half2*)(hibase + off)      = hp;
    *(__half2*)(hibase + LO + off) = lp;
}

// ---------------- weight prep (fp16 hi only) ----------------
__global__ void prep_w_k(const float* __restrict__ w, __half* __restrict__ wt,
                         int Cout, int Cin) {
    int total = (Cin / 32) * 9 * Cout * 32;
    for (int idx = blockIdx.x * blockDim.x + threadIdx.x; idx < total;
         idx += gridDim.x * blockDim.x) {
        int ci  = idx & 31;
        int n   = (idx >> 5) % Cout;
        int tap = (idx / (32 * Cout)) % 9;
        int c32 = idx / (32 * Cout * 9);
        int dy = tap / 3, dx = tap % 3;
        float v = w[(((size_t)n * Cin + c32 * 32 + ci) * 3 + dy) * 3 + dx];
        wt[(((size_t)(c32 * 3 + dy) * 3 + dx) * Cout + n) * 32 + ci] = __float2half(v);
    }
}

// ---------------- input prep: transpose + fp16 hi/lo split ----------------
__global__ __launch_bounds__(256) void prep_x_k(const float* __restrict__ x,
                                                __half* __restrict__ x0s,
                                                __half* __restrict__ x1s) {
    __shared__ float sf[64][132];
    const int tid = threadIdx.x;
    const int px0 = blockIdx.x * 128;
    const int img = blockIdx.y;
    const int ag  = blockIdx.z;
    const float* src = x + ((size_t)(ag * 4 + img) * 64) * HW;
    for (int i = tid; i < 64 * 128; i += 256) {
        int c = i >> 7, px = i & 127;
        sf[c][px] = src[(size_t)c * HW + px0 + px];
    }
    __syncthreads();
    __half* dst = (ag ? x1s : x0s) + (size_t)img * 2 * LO;
    for (int i = tid; i < 128 * 8; i += 256) {
        int px = i >> 3, q = i & 7;
        __half hb[8], lb[8];
#pragma unroll
        for (int j = 0; j < 8; j++) {
            float v = sf[q * 8 + j][px];
            hb[j] = __float2half(v);
            lb[j] = __float2half(v - __half2float(hb[j]));
        }
        size_t o = (size_t)(px0 + px) * 64 + q * 8;
        *(uint4*)(dst + o)      = *(const uint4*)hb;
        *(uint4*)(dst + LO + o) = *(const uint4*)lb;
    }
}

// ---------------- fused implicit-GEMM conv (HMMA fp16 2-product) ----------------
struct Srcs { const __half* p[6]; };

// MODE 0 (msg, N=64):   agg = 0.5*(x0 + conv+b) -> split store (aggs)
// MODE 1 (gates,N=128): c<64: rhs = split(sigmoid*h); c>=64: u = sigmoid (ch-last fp32)
// MODE 2 (can,  N=64):  hn = (1-u)*h + u*tanh(conv+b) -> fp32 out + split (hs)
template<int MODE, int N>
__global__ __launch_bounds__(256, 2) void conv_mma_k(
    Srcs srcs, long long imgStride,
    const __half* __restrict__ wt,
    const float* __restrict__ bias,
    int nchunks,
    const float* __restrict__ fpA,
    const float* __restrict__ fpB,
    __half* __restrict__ splitOut,
    float* __restrict__ fpOut)
{
    extern __shared__ char dsm[];
    constexpr int WM  = 4;
    constexpr int MF  = 2;
    constexpr int NPW = N / 2;
    constexpr int NFP = NPW / 16;
    constexpr int NF  = NPW / 8;
    constexpr int A_BYTES = 2 * 3 * 132 * 40 * 2;      // 63,360
    constexpr int B_BYTES = 3 * N * 40 * 2;
    constexpr bool DB = (N == 64);

    const int tid  = threadIdx.x;
    const int warp = tid >> 5, lane = tid & 31;
    const int xt = blockIdx.x, y = blockIdx.y, img = blockIdx.z;
    const int x0 = (xt < 2) ? xt * 128 : 224;

    char* base = (char*)(((uintptr_t)dsm + 127) & ~(uintptr_t)127);
    const uint32_t sA = smem_u32(base);
    const uint32_t sB = sA + A_BYTES;

    const int mbase = (warp & 3) * 32;
    const int nbase = (warp >> 2) * NPW;

    float acc[MF][NF][4];
#pragma unroll
    for (int i = 0; i < MF; i++)
#pragma unroll
        for (int j = 0; j < NF; j++)
#pragma unroll
            for (int q = 0; q < 4; q++) acc[i][j][q] = 0.f;

    const int a_row = lane & 15, a_col = (lane >> 4) * 8;
    const int b_n   = ((lane & 16) >> 1) + (lane & 7);
    const int b_k   = ((lane >> 3) & 1) * 8;

    const int G = nchunks * 3;

    auto stageA = [&](int chunk) {
        const __half* sp = srcs.p[chunk] + (size_t)img * imgStride;
        for (int idx = tid; idx < 3 * 130 * 2 * 4; idx += 256) {
            int quad = idx & 3;
            int hl   = (idx >> 2) & 1;
            int px   = (idx >> 3) % 130;
            int r    = idx / (130 * 2 * 4);
            int gy = y - 1 + r, gx = x0 - 1 + px;
            uint32_t dst = sA + (uint32_t)(((hl * 3 + r) * 132 + px) * 80 + quad * 16);
            if ((unsigned)gy < (unsigned)HH && (unsigned)gx < (unsigned)WW)
                cp16(dst, sp + hl * LO + (size_t)(gy * WW + gx) * 64 + quad * 8);
            else
                sts_zero16(dst);
        }
    };
    auto stageB = [&](int g, int bbuf) {
        const __half* ws = wt + (size_t)g * 3 * N * 32;
        uint32_t bb = sB + bbuf * B_BYTES;
        for (int idx = tid; idx < 3 * N * 4; idx += 256) {
            int quad = idx & 3;
            int n    = (idx >> 2) % N;
            int dx   = idx / (4 * N);
            cp16(bb + (uint32_t)((dx * N + n) * 80 + quad * 16),
                 ws + ((size_t)dx * N + n) * 32 + quad * 8);
        }
    };

    if (DB) { stageB(0, 0); cp_commit(); }

    for (int g = 0; g < G; g++) {
        const int chunk = g / 3, dy = g - chunk * 3;
        const int bbuf = DB ? (g & 1) : 0;

        __syncthreads();
        if (dy == 0) { stageA(chunk); cp_commit(); }
        if (DB) {
            if (g + 1 < G) { stageB(g + 1, (g + 1) & 1); cp_commit(); }
            if (g + 1 < G) cp_wait<1>(); else cp_wait<0>();
        } else {
            stageB(g, 0); cp_commit();
            cp_wait<0>();
        }
        __syncthreads();

        const uint32_t bb = sB + bbuf * B_BYTES;
#pragma unroll
        for (int kt = 0; kt < 2; kt++) {
#pragma unroll
            for (int dx = 0; dx < 3; dx++) {
                uint32_t a[2][MF][4];
#pragma unroll
                for (int hl = 0; hl < 2; hl++)
#pragma unroll
                    for (int mf = 0; mf < MF; mf++) {
                        uint32_t addr = sA + (uint32_t)((((hl * 3 + dy) * 132 +
                            (mbase + mf * 16 + a_row + dx)) * 40 +
                            kt * 16 + a_col) * 2);
                        ldsm_x4(a[hl][mf], addr);
                    }
#pragma unroll
                for (int nfp = 0; nfp < NFP; nfp++) {
                    uint32_t t[4];
                    uint32_t addr = bb + (uint32_t)(((dx * N +
                        (nbase + nfp * 16 + b_n)) * 40 +
                        kt * 16 + b_k) * 2);
                    ldsm_x4(t, addr);
#pragma unroll
                    for (int half_ = 0; half_ < 2; half_++) {
                        uint32_t bfrag[2] = {t[half_ * 2], t[half_ * 2 + 1]};
                        int nf = nfp * 2 + half_;
#pragma unroll
                        for (int mf = 0; mf < MF; mf++) {
                            mma16816(acc[mf][nf], a[0][mf], bfrag);  // hi*B
                            mma16816(acc[mf][nf], a[1][mf], bfrag);  // lo*B
                        }
                    }
                }
            }
        }
    }

    // ---- epilogue (c pairs packed) ----
    const int gq = lane >> 2, q = lane & 3;
#pragma unroll
    for (int mf = 0; mf < MF; mf++) {
#pragma unroll
        for (int nf = 0; nf < NF; nf++) {
#pragma unroll
            for (int mh = 0; mh < 2; mh++) {
                int m  = mbase + mf * 16 + gq + mh * 8;
                int c0 = nbase + nf * 8 + q * 2;
                float v0 = acc[mf][nf][mh * 2 + 0] + bias[c0];
                float v1 = acc[mf][nf][mh * 2 + 1] + bias[c0 + 1];
                size_t pix = (size_t)y * WW + (x0 + m);
                size_t o0 = (size_t)c0 * HW + pix;
                size_t o1 = o0 + HW;
                if (MODE == 0) {
                    const float* xs = fpA + (size_t)img * 64 * HW;
                    float a0 = 0.5f * (xs[o0] + v0);
                    float a1 = 0.5f * (xs[o1] + v1);
                    split_store2(splitOut + (size_t)img * 2 * LO, pix * 64 + c0, a0, a1);
                } else if (MODE == 1) {
                    float s0 = 1.f / (1.f + __expf(-v0));
                    float s1 = 1.f / (1.f + __expf(-v1));
                    if (c0 < 64) {
                        float h0 = fpA ? fpA[o0] : 0.f;
                        float h1 = fpA ? fpA[o1] : 0.f;
                        split_store2(splitOut, pix * 64 + c0, s0 * h0, s1 * h1);
                    } else {
                        float2 up; up.x = s0; up.y = s1;
                        *(float2*)(fpOut + pix * 64 + (c0 - 64)) = up;
                    }
                } else {
                    float cn0 = fast_tanh(v0), cn1 = fast_tanh(v1);
                    float2 up = *(const float2*)(fpB + pix * 64 + c0);
                    float h0 = fpA ? fpA[o0] : 0.f;
                    float h1 = fpA ? fpA[o1] : 0.f;
                    float hn0 = (1.f - up.x) * h0 + up.x * cn0;
                    float hn1 = (1.f - up.y) * h1 + up.y * cn1;
                    fpOut[o0] = hn0;
                    fpOut[o1] = hn1;
                    split_store2(splitOut, pix * 64 + c0, hn0, hn1);
                }
            }
        }
    }
}

// ---------------- host launcher ----------------
extern "C" void kernel_launch(void* const* d_in, const int* in_sizes, int n_in,
                              void* d_out, int out_size)
{
    const float* x       = (const float*)d_in[0];
    const float* msg_w   = (const float*)d_in[1];
    const float* msg_b   = (const float*)d_in[2];
    const float* gates_w = (const float*)d_in[3];
    const float* gates_b = (const float*)d_in[4];
    const float* can_w   = (const float*)d_in[5];
    const float* can_b   = (const float*)d_in[6];
    float* out = (float*)d_out;

    __half *x0s, *x1s, *aggs, *hs, *rhs, *wtm, *wtg, *wtc;
    float* u;
    cudaGetSymbolAddress((void**)&x0s,  g_x0s);
    cudaGetSymbolAddress((void**)&x1s,  g_x1s);
    cudaGetSymbolAddress((void**)&aggs, g_aggs);
    cudaGetSymbolAddress((void**)&hs,   g_hs);
    cudaGetSymbolAddress((void**)&rhs,  g_rhs);
    cudaGetSymbolAddress((void**)&u,    g_u);
    cudaGetSymbolAddress((void**)&wtm,  g_wt_msg);
    cudaGetSymbolAddress((void**)&wtg,  g_wt_gates);
    cudaGetSymbolAddress((void**)&wtc,  g_wt_can);

    // One-time stream/event creation (first call is the uncaptured correctness
    // run; captured calls reuse the same handles -> identical graph each time).
    static cudaStream_t sMsg = nullptr;
    static cudaEvent_t evP = nullptr, evM[4] = {nullptr, nullptr, nullptr, nullptr};
    if (!sMsg) {
        cudaStreamCreateWithFlags(&sMsg, cudaStreamNonBlocking);
        cudaEventCreateWithFlags(&evP, cudaEventDisableTiming);
        for (int i = 0; i < 4; i++)
            cudaEventCreateWithFlags(&evM[i], cudaEventDisableTiming);
    }

    const int A_BYTES = 2 * 3 * 132 * 40 * 2;                   // 63,360
    const int smem64  = A_BYTES + 2 * (3 * 64 * 40 * 2) + 256;  // ~94.3KB
    const int smem128 = A_BYTES + 3 * 128 * 40 * 2 + 256;       // ~94.3KB
    cudaFuncSetAttribute(conv_mma_k<0,64>,  cudaFuncAttributeMaxDynamicSharedMemorySize, smem64);
    cudaFuncSetAttribute(conv_mma_k<1,128>, cudaFuncAttributeMaxDynamicSharedMemorySize, smem128);
    cudaFuncSetAttribute(conv_mma_k<2,64>,  cudaFuncAttributeMaxDynamicSharedMemorySize, smem64);

    // ---- prep on main stream ----
    prep_w_k<<<128, 256>>>(msg_w,   wtm, 64,  128);
    prep_w_k<<<128, 256>>>(gates_w, wtg, 128, 192);
    prep_w_k<<<128, 256>>>(can_w,   wtc, 64,  192);
    prep_x_k<<<dim3(HW / 128, 4, 2), 256>>>(x, x0s, x1s);
    cudaEventRecord(evP, 0);

    const long long imgStrideHf = 2LL * HW * 64;

    // ---- Phase A on msg stream: one launch per image, event after each ----
    cudaStreamWaitEvent(sMsg, evP, 0);
    for (int t = 0; t < 4; t++) {
        Srcs s{};
        s.p[0] = x0s + (size_t)t * imgStrideHf;
        s.p[1] = x0s + (size_t)t * imgStrideHf + 32;
        s.p[2] = x1s + (size_t)t * imgStrideHf;
        s.p[3] = x1s + (size_t)t * imgStrideHf + 32;
        conv_mma_k<0,64><<<dim3(3, HH, 1), 256, smem64, sMsg>>>(
            s, 0, wtm, msg_b, 4,
            x + (size_t)t * 64 * HW, nullptr,
            aggs + (size_t)t * imgStrideHf, nullptr);
        cudaEventRecord(evM[t], sMsg);
    }

    // ---- Phase B on main stream: gates_t waits only on msg_t ----
    for (int t = 0; t < 4; t++) {
        cudaStreamWaitEvent(0, evM[t], 0);
        const __half* x0t = x0s  + (size_t)t * imgStrideHf;
        const __half* agt = aggs + (size_t)t * imgStrideHf;
        const float* hp = t ? (out + (size_t)(t - 1) * 64 * HW) : nullptr;
        {
            Srcs s{};
            s.p[0] = x0t; s.p[1] = x0t + 32;
            s.p[2] = agt; s.p[3] = agt + 32;
            s.p[4] = hs;  s.p[5] = hs + 32;
            conv_mma_k<1,128><<<dim3(3, HH, 1), 256, smem128>>>(
                s, 0, wtg, gates_b, t ? 6 : 4, hp, nullptr, rhs, u);
        }
        {
            Srcs s{};
            s.p[0] = x0t; s.p[1] = x0t + 32;
            s.p[2] = agt; s.p[3] = agt + 32;
            s.p[4] = rhs; s.p[5] = rhs + 32;
            conv_mma_k<2,64><<<dim3(3, HH, 1), 256, smem64>>>(
                s, 0, wtc, can_b, t ? 6 : 4, hp, u, hs, out + (size_t)t * 64 * HW);
        }
    }
}

// round 14
// speedup vs baseline: 8.6264x; 1.5354x over previous
#include <cuda_runtime.h>
#include <cuda_fp16.h>
#include <math.h>
#include <stdint.h>

#define HH 200
#define WW 352
#define HW 70400

// ---------------- static scratch ----------------
// channel-last fp16 planes: [img][HW][64]
__device__ __half g_x0s [4 * HW * 64];
__device__ __half g_x1s [4 * HW * 64];
__device__ __half g_aggs[4 * HW * 64];
__device__ __half g_hs  [HW * 64];
__device__ __half g_rhs [HW * 64];
__device__ float g_u[HW * 64];                 // update gate, CHANNEL-LAST [pix][c]
// fp16 weights: [g=c32*3+dy][dx][n][32ci]
__device__ __half g_wt_msg  [4 * 9 * 64  * 32];
__device__ __half g_wt_gates[6 * 9 * 128 * 32];
__device__ __half g_wt_can  [6 * 9 * 64  * 32];

// ---------------- helpers ----------------
__device__ __forceinline__ uint32_t smem_u32(const void* p) {
    uint32_t a;
    asm("{ .reg .u64 t; cvta.to.shared.u64 t, %1; cvt.u32.u64 %0, t; }" : "=r"(a) : "l"(p));
    return a;
}
__device__ __forceinline__ void cp16(uint32_t dst, const void* src) {
    asm volatile("cp.async.ca.shared.global [%0], [%1], 16;" :: "r"(dst), "l"(src));
}
__device__ __forceinline__ void cp_commit() {
    asm volatile("cp.async.commit_group;" ::: "memory");
}
template<int N_> __device__ __forceinline__ void cp_wait() {
    asm volatile("cp.async.wait_group %0;" :: "n"(N_) : "memory");
}
__device__ __forceinline__ void sts_zero16(uint32_t a) {
    asm volatile("st.shared.v4.b32 [%0], {%1,%1,%1,%1};" :: "r"(a), "r"(0u) : "memory");
}
__device__ __forceinline__ void ldsm_x4(uint32_t* r, uint32_t addr) {
    asm volatile("ldmatrix.sync.aligned.m8n8.x4.shared.b16 {%0,%1,%2,%3}, [%4];"
        : "=r"(r[0]), "=r"(r[1]), "=r"(r[2]), "=r"(r[3]) : "r"(addr));
}
__device__ __forceinline__ void mma16816(float* d, const uint32_t* a, const uint32_t* b) {
    asm volatile("mma.sync.aligned.m16n8k16.row.col.f32.f16.f16.f32 "
        "{%0,%1,%2,%3},{%4,%5,%6,%7},{%8,%9},{%0,%1,%2,%3};"
        : "+f"(d[0]), "+f"(d[1]), "+f"(d[2]), "+f"(d[3])
        : "r"(a[0]), "r"(a[1]), "r"(a[2]), "r"(a[3]), "r"(b[0]), "r"(b[1]));
}
__device__ __forceinline__ float fast_tanh(float v) {
    float e = __expf(2.f * v);
    return 1.f - 2.f / (e + 1.f);
}
__device__ __forceinline__ void store2(__half* hibase, size_t off, float v0, float v1) {
    __half2 hp; hp.x = __float2half(v0); hp.y = __float2half(v1);
    *(__half2*)(hibase + off) = hp;
}

// ---------------- weight prep (fp16) ----------------
__global__ void prep_w_k(const float* __restrict__ w, __half* __restrict__ wt,
                         int Cout, int Cin) {
    int total = (Cin / 32) * 9 * Cout * 32;
    for (int idx = blockIdx.x * blockDim.x + threadIdx.x; idx < total;
         idx += gridDim.x * blockDim.x) {
        int ci  = idx & 31;
        int n   = (idx >> 5) % Cout;
        int tap = (idx / (32 * Cout)) % 9;
        int c32 = idx / (32 * Cout * 9);
        int dy = tap / 3, dx = tap % 3;
        float v = w[(((size_t)n * Cin + c32 * 32 + ci) * 3 + dy) * 3 + dx];
        wt[(((size_t)(c32 * 3 + dy) * 3 + dx) * Cout + n) * 32 + ci] = __float2half(v);
    }
}

// ---------------- input prep: transpose to channel-last fp16 ----------------
__global__ __launch_bounds__(256) void prep_x_k(const float* __restrict__ x,
                                                __half* __restrict__ x0s,
                                                __half* __restrict__ x1s) {
    __shared__ float sf[64][132];
    const int tid = threadIdx.x;
    const int px0 = blockIdx.x * 128;
    const int img = blockIdx.y;
    const int ag  = blockIdx.z;
    const float* src = x + ((size_t)(ag * 4 + img) * 64) * HW;
    for (int i = tid; i < 64 * 128; i += 256) {
        int c = i >> 7, px = i & 127;
        sf[c][px] = src[(size_t)c * HW + px0 + px];
    }
    __syncthreads();
    __half* dst = (ag ? x1s : x0s) + (size_t)img * HW * 64;
    for (int i = tid; i < 128 * 8; i += 256) {
        int px = i >> 3, q = i & 7;
        __half hb[8];
#pragma unroll
        for (int j = 0; j < 8; j++)
            hb[j] = __float2half(sf[q * 8 + j][px]);
        *(uint4*)(dst + (size_t)(px0 + px) * 64 + q * 8) = *(const uint4*)hb;
    }
}

// ---------------- fused implicit-GEMM conv (HMMA fp16 single-product) ----------------
struct Srcs { const __half* p[6]; };

// MODE 0 (msg, N=64):   agg = 0.5*(x0 + conv+b) -> fp16 store (aggs)
// MODE 1 (gates,N=128): c<64: rhs = fp16(sigmoid*h); c>=64: u = sigmoid (ch-last fp32)
// MODE 2 (can,  N=64):  hn = (1-u)*h + u*tanh(conv+b) -> fp32 out + fp16 (hs)
template<int MODE, int N>
__global__ __launch_bounds__(256, 2) void conv_mma_k(
    Srcs srcs, long long imgStride,
    const __half* __restrict__ wt,
    const float* __restrict__ bias,
    int nchunks,
    const float* __restrict__ fpA,            // M0: x0 fp32; M1/M2: h fp32 (NCHW)
    const float* __restrict__ fpB,            // M2: u (channel-last)
    __half* __restrict__ halfOut,             // M0: aggs; M1: rhs; M2: hs
    float* __restrict__ fpOut)                // M1: u (ch-last); M2: d_out slice
{
    extern __shared__ char dsm[];
    constexpr int WM  = 4;
    constexpr int MF  = 2;
    constexpr int NPW = N / 2;
    constexpr int NFP = NPW / 16;
    constexpr int NF  = NPW / 8;
    constexpr int A_BYTES = 3 * 130 * 80;              // 31,200
    constexpr int B_BYTES = 3 * N * 40 * 2;            // per buffer

    const int tid  = threadIdx.x;
    const int warp = tid >> 5, lane = tid & 31;
    const int xt = blockIdx.x, y = blockIdx.y, img = blockIdx.z;
    const int x0 = (xt < 2) ? xt * 128 : 224;

    char* base = (char*)(((uintptr_t)dsm + 127) & ~(uintptr_t)127);
    const uint32_t sA = smem_u32(base);
    const uint32_t sB = sA + A_BYTES;

    const int mbase = (warp & 3) * 32;
    const int nbase = (warp >> 2) * NPW;

    float acc[MF][NF][4];
#pragma unroll
    for (int i = 0; i < MF; i++)
#pragma unroll
        for (int j = 0; j < NF; j++)
#pragma unroll
            for (int q = 0; q < 4; q++) acc[i][j][q] = 0.f;

    const int a_row = lane & 15, a_col = (lane >> 4) * 8;
    const int b_n   = ((lane & 16) >> 1) + (lane & 7);
    const int b_k   = ((lane >> 3) & 1) * 8;

    const int G = nchunks * 3;

    auto stageA = [&](int chunk) {
        const __half* sp = srcs.p[chunk] + (size_t)img * imgStride;
        for (int idx = tid; idx < 3 * 130 * 4; idx += 256) {
            int quad = idx & 3;
            int px   = (idx >> 2) % 130;
            int r    = idx / 520;
            int gy = y - 1 + r, gx = x0 - 1 + px;
            uint32_t dst = sA + (uint32_t)((r * 130 + px) * 80 + quad * 16);
            if ((unsigned)gy < (unsigned)HH && (unsigned)gx < (unsigned)WW)
                cp16(dst, sp + (size_t)(gy * WW + gx) * 64 + quad * 8);
            else
                sts_zero16(dst);
        }
    };
    auto stageB = [&](int g, int bbuf) {
        const __half* ws = wt + (size_t)g * 3 * N * 32;
        uint32_t bb = sB + bbuf * B_BYTES;
        for (int idx = tid; idx < 3 * N * 4; idx += 256) {
            int quad = idx & 3;
            int n    = (idx >> 2) % N;
            int dx   = idx / (4 * N);
            cp16(bb + (uint32_t)((dx * N + n) * 80 + quad * 16),
                 ws + ((size_t)dx * N + n) * 32 + quad * 8);
        }
    };

    stageB(0, 0);
    cp_commit();

    for (int g = 0; g < G; g++) {
        const int chunk = g / 3, dy = g - chunk * 3;
        const int bbuf = g & 1;

        __syncthreads();                      // prior compute done with A + B[bbuf^1]
        if (dy == 0) { stageA(chunk); cp_commit(); }
        if (g + 1 < G) { stageB(g + 1, bbuf ^ 1); cp_commit(); }
        if (g + 1 < G) cp_wait<1>(); else cp_wait<0>();   // B(g)+A drained, B(g+1) in flight
        __syncthreads();

        const uint32_t bb = sB + bbuf * B_BYTES;
#pragma unroll
        for (int kt = 0; kt < 2; kt++) {
#pragma unroll
            for (int dx = 0; dx < 3; dx++) {
                uint32_t a[MF][4];
#pragma unroll
                for (int mf = 0; mf < MF; mf++) {
                    uint32_t addr = sA + (uint32_t)(((dy * 130 +
                        (mbase + mf * 16 + a_row + dx)) * 40 +
                        kt * 16 + a_col) * 2);
                    ldsm_x4(a[mf], addr);
                }
#pragma unroll
                for (int nfp = 0; nfp < NFP; nfp++) {
                    uint32_t t[4];
                    uint32_t addr = bb + (uint32_t)(((dx * N +
                        (nbase + nfp * 16 + b_n)) * 40 +
                        kt * 16 + b_k) * 2);
                    ldsm_x4(t, addr);
#pragma unroll
                    for (int half_ = 0; half_ < 2; half_++) {
                        uint32_t bfrag[2] = {t[half_ * 2], t[half_ * 2 + 1]};
                        int nf = nfp * 2 + half_;
#pragma unroll
                        for (int mf = 0; mf < MF; mf++)
                            mma16816(acc[mf][nf], a[mf], bfrag);
                    }
                }
            }
        }
    }

    // ---- epilogue (c pairs packed) ----
    const int gq = lane >> 2, q = lane & 3;
#pragma unroll
    for (int mf = 0; mf < MF; mf++) {
#pragma unroll
        for (int nf = 0; nf < NF; nf++) {
#pragma unroll
            for (int mh = 0; mh < 2; mh++) {
                int m  = mbase + mf * 16 + gq + mh * 8;
                int c0 = nbase + nf * 8 + q * 2;
                float v0 = acc[mf][nf][mh * 2 + 0] + bias[c0];
                float v1 = acc[mf][nf][mh * 2 + 1] + bias[c0 + 1];
                size_t pix = (size_t)y * WW + (x0 + m);
                size_t o0 = (size_t)c0 * HW + pix;
                size_t o1 = o0 + HW;
                if (MODE == 0) {
                    const float* xs = fpA + (size_t)img * 64 * HW;
                    float a0 = 0.5f * (xs[o0] + v0);
                    float a1 = 0.5f * (xs[o1] + v1);
                    store2(halfOut + (size_t)img * HW * 64, pix * 64 + c0, a0, a1);
                } else if (MODE == 1) {
                    float s0 = 1.f / (1.f + __expf(-v0));
                    float s1 = 1.f / (1.f + __expf(-v1));
                    if (c0 < 64) {
                        float h0 = fpA ? fpA[o0] : 0.f;
                        float h1 = fpA ? fpA[o1] : 0.f;
                        store2(halfOut, pix * 64 + c0, s0 * h0, s1 * h1);
                    } else {
                        float2 up; up.x = s0; up.y = s1;
                        *(float2*)(fpOut + pix * 64 + (c0 - 64)) = up;
                    }
                } else {
                    float cn0 = fast_tanh(v0), cn1 = fast_tanh(v1);
                    float2 up = *(const float2*)(fpB + pix * 64 + c0);
                    float h0 = fpA ? fpA[o0] : 0.f;
                    float h1 = fpA ? fpA[o1] : 0.f;
                    float hn0 = (1.f - up.x) * h0 + up.x * cn0;
                    float hn1 = (1.f - up.y) * h1 + up.y * cn1;
                    fpOut[o0] = hn0;
                    fpOut[o1] = hn1;
                    store2(halfOut, pix * 64 + c0, hn0, hn1);
                }
            }
        }
    }
}

// ---------------- host launcher ----------------
extern "C" void kernel_launch(void* const* d_in, const int* in_sizes, int n_in,
                              void* d_out, int out_size)
{
    const float* x       = (const float*)d_in[0];
    const float* msg_w   = (const float*)d_in[1];
    const float* msg_b   = (const float*)d_in[2];
    const float* gates_w = (const float*)d_in[3];
    const float* gates_b = (const float*)d_in[4];
    const float* can_w   = (const float*)d_in[5];
    const float* can_b   = (const float*)d_in[6];
    float* out = (float*)d_out;

    __half *x0s, *x1s, *aggs, *hs, *rhs, *wtm, *wtg, *wtc;
    float* u;
    cudaGetSymbolAddress((void**)&x0s,  g_x0s);
    cudaGetSymbolAddress((void**)&x1s,  g_x1s);
    cudaGetSymbolAddress((void**)&aggs, g_aggs);
    cudaGetSymbolAddress((void**)&hs,   g_hs);
    cudaGetSymbolAddress((void**)&rhs,  g_rhs);
    cudaGetSymbolAddress((void**)&u,    g_u);
    cudaGetSymbolAddress((void**)&wtm,  g_wt_msg);
    cudaGetSymbolAddress((void**)&wtg,  g_wt_gates);
    cudaGetSymbolAddress((void**)&wtc,  g_wt_can);

    static cudaStream_t sMsg = nullptr;
    static cudaEvent_t evP = nullptr, evM[4] = {nullptr, nullptr, nullptr, nullptr};
    if (!sMsg) {
        cudaStreamCreateWithFlags(&sMsg, cudaStreamNonBlocking);
        cudaEventCreateWithFlags(&evP, cudaEventDisableTiming);
        for (int i = 0; i < 4; i++)
            cudaEventCreateWithFlags(&evM[i], cudaEventDisableTiming);
    }

    const int A_BYTES = 3 * 130 * 80;                           // 31,200
    const int smem64  = A_BYTES + 2 * (3 * 64 * 40 * 2) + 256;  // ~62.2KB
    const int smem128 = A_BYTES + 2 * (3 * 128 * 40 * 2) + 256; // ~92.9KB
    cudaFuncSetAttribute(conv_mma_k<0,64>,  cudaFuncAttributeMaxDynamicSharedMemorySize, smem64);
    cudaFuncSetAttribute(conv_mma_k<1,128>, cudaFuncAttributeMaxDynamicSharedMemorySize, smem128);
    cudaFuncSetAttribute(conv_mma_k<2,64>,  cudaFuncAttributeMaxDynamicSharedMemorySize, smem64);

    // ---- prep on main stream ----
    prep_w_k<<<128, 256>>>(msg_w,   wtm, 64,  128);
    prep_w_k<<<128, 256>>>(gates_w, wtg, 128, 192);
    prep_w_k<<<128, 256>>>(can_w,   wtc, 64,  192);
    prep_x_k<<<dim3(HW / 128, 4, 2), 256>>>(x, x0s, x1s);
    cudaEventRecord(evP, 0);

    const long long imgStrideHf = (long long)HW * 64;

    // ---- Phase A on msg stream: one launch per image ----
    cudaStreamWaitEvent(sMsg, evP, 0);
    for (int t = 0; t < 4; t++) {
        Srcs s{};
        s.p[0] = x0s + (size_t)t * imgStrideHf;
        s.p[1] = x0s + (size_t)t * imgStrideHf + 32;
        s.p[2] = x1s + (size_t)t * imgStrideHf;
        s.p[3] = x1s + (size_t)t * imgStrideHf + 32;
        conv_mma_k<0,64><<<dim3(3, HH, 1), 256, smem64, sMsg>>>(
            s, 0, wtm, msg_b, 4,
            x + (size_t)t * 64 * HW, nullptr,
            aggs + (size_t)t * imgStrideHf, nullptr);
        cudaEventRecord(evM[t], sMsg);
    }

    // ---- Phase B on main stream ----
    for (int t = 0; t < 4; t++) {
        cudaStreamWaitEvent(0, evM[t], 0);
        const __half* x0t = x0s  + (size_t)t * imgStrideHf;
        const __half* agt = aggs + (size_t)t * imgStrideHf;
        const float* hp = t ? (out + (size_t)(t - 1) * 64 * HW) : nullptr;
        {
            Srcs s{};
            s.p[0] = x0t; s.p[1] = x0t + 32;
            s.p[2] = agt; s.p[3] = agt + 32;
            s.p[4] = hs;  s.p[5] = hs + 32;
            conv_mma_k<1,128><<<dim3(3, HH, 1), 256, smem128>>>(
                s, 0, wtg, gates_b, t ? 6 : 4, hp, nullptr, rhs, u);
        }
        {
            Srcs s{};
            s.p[0] = x0t; s.p[1] = x0t + 32;
            s.p[2] = agt; s.p[3] = agt + 32;
            s.p[4] = rhs; s.p[5] = rhs + 32;
            conv_mma_k<2,64><<<dim3(3, HH, 1), 256, smem64>>>(
                s, 0, wtc, can_b, t ? 6 : 4, hp, u, hs, out + (size_t)t * 64 * HW);
        }
    }
}